// round 2
// baseline (speedup 1.0000x reference)
#include <cuda_runtime.h>
#include <math.h>

// Problem constants (shapes fixed by the dataset): DN=DE=64, H=128.
#define T_EDGES 64
#define THREADS 256

// Shared memory layout (floats):
//  sW : 128*128 = 16384   staged weight matrix (max 64KB)
//  sA : 64*64   =  4096   hs, later reused for eh_new
//  sT : 64*64   =  4096   t = hs*hd
//  sX : 64*128  =  8192   x1 / x2
//  sM : 64*128  =  8192   m1 / p = m1*m2
//  sB : 128               bias
//  + 128 ints (src/dst indices)
#define SMEM_FLOATS (16384 + 4096 + 4096 + 8192 + 8192 + 128)
#define SMEM_BYTES  (SMEM_FLOATS * 4 + 128 * 4)

__global__ void init_out(const float4* __restrict__ h4, float4* __restrict__ o4, int n4) {
    int i = blockIdx.x * blockDim.x + threadIdx.x;
    int stride = gridDim.x * blockDim.x;
    for (int j = i; j < n4; j += stride) o4[j] = h4[j];
}

__device__ __forceinline__ void load_w(float* s, const float* __restrict__ g, int nfloats, int tid) {
    const float4* g4 = (const float4*)g;
    float4* s4 = (float4*)s;
    int n4 = nfloats >> 2;
    for (int i = tid; i < n4; i += THREADS) s4[i] = g4[i];
}

// C[4][8] = A[64 x DIN] (rows row0..row0+3) @ W[DIN x 128] (cols c0..c0+7)
template<int DIN, int LDA>
__device__ __forceinline__ void gemm_acc8(const float* __restrict__ sA_, const float* __restrict__ sW_,
                                          int row0, int c0, float acc[4][8]) {
#pragma unroll
    for (int r = 0; r < 4; ++r)
#pragma unroll
        for (int c = 0; c < 8; ++c) acc[r][c] = 0.f;
#pragma unroll 4
    for (int k = 0; k < DIN; ++k) {
        float4 b0 = *(const float4*)(sW_ + k * 128 + c0);
        float4 b1 = *(const float4*)(sW_ + k * 128 + c0 + 4);
        float bv[8] = {b0.x, b0.y, b0.z, b0.w, b1.x, b1.y, b1.z, b1.w};
        float av[4];
#pragma unroll
        for (int r = 0; r < 4; ++r) av[r] = sA_[(row0 + r) * LDA + k];
#pragma unroll
        for (int r = 0; r < 4; ++r)
#pragma unroll
            for (int c = 0; c < 8; ++c)
                acc[r][c] = fmaf(av[r], bv[c], acc[r][c]);
    }
}

// C[4][4] = A[64 x DIN] @ W[DIN x 64] (cols c0..c0+3)
template<int DIN, int LDA>
__device__ __forceinline__ void gemm_acc4(const float* __restrict__ sA_, const float* __restrict__ sW_,
                                          int row0, int c0, float acc[4][4]) {
#pragma unroll
    for (int r = 0; r < 4; ++r)
#pragma unroll
        for (int c = 0; c < 4; ++c) acc[r][c] = 0.f;
#pragma unroll 4
    for (int k = 0; k < DIN; ++k) {
        float4 b0 = *(const float4*)(sW_ + k * 64 + c0);
        float bv[4] = {b0.x, b0.y, b0.z, b0.w};
        float av[4];
#pragma unroll
        for (int r = 0; r < 4; ++r) av[r] = sA_[(row0 + r) * LDA + k];
#pragma unroll
        for (int r = 0; r < 4; ++r)
#pragma unroll
            for (int c = 0; c < 4; ++c)
                acc[r][c] = fmaf(av[r], bv[c], acc[r][c]);
    }
}

__global__ __launch_bounds__(THREADS, 1)
void edge_kernel(const float* __restrict__ h, const float* __restrict__ eh,
                 const float* __restrict__ Wn1, const float* __restrict__ bn1,
                 const float* __restrict__ Wn2,
                 const float* __restrict__ We1, const float* __restrict__ be1,
                 const float* __restrict__ We2,
                 const float* __restrict__ Wc, const float* __restrict__ Wue,
                 const int* __restrict__ src, const int* __restrict__ dst,
                 float* __restrict__ out, int E)
{
    extern __shared__ float smem[];
    float* sW = smem;             // 16384
    float* sA = sW + 16384;       // 4096
    float* sT = sA + 4096;        // 4096
    float* sX = sT + 4096;        // 8192
    float* sM = sX + 8192;        // 8192
    float* sB = sM + 8192;        // 128
    int* sSrc = (int*)(sB + 128); // 64
    int* sDst = sSrc + 64;        // 64

    const int tid = threadIdx.x;
    const int e0 = blockIdx.x * T_EDGES;

    // --- indices (clamped; out-of-range edges are masked at the atomic) ---
    if (tid < T_EDGES) {
        int eg = e0 + tid;
        if (eg >= E) eg = E - 1;
        sSrc[tid] = src[eg];
        sDst[tid] = dst[eg];
    }
    __syncthreads();

    // --- gather hs -> sA, t = hs*hd -> sT; concurrently stage W_node1 + b1 ---
    for (int i = tid; i < T_EDGES * 16; i += THREADS) {
        int e = i >> 4;
        int d4 = i & 15;
        const float4* hsrow = (const float4*)(h + (size_t)sSrc[e] * 64);
        const float4* hdrow = (const float4*)(h + (size_t)sDst[e] * 64);
        float4 a = hsrow[d4];
        float4 b = hdrow[d4];
        ((float4*)(sA + e * 64))[d4] = a;
        ((float4*)(sT + e * 64))[d4] = make_float4(a.x * b.x, a.y * b.y, a.z * b.z, a.w * b.w);
    }
    load_w(sW, Wn1, 64 * 128, tid);
    if (tid < 128) sB[tid] = bn1[tid];
    __syncthreads();

    const int cg = tid & 15;
    const int rg = tid >> 4;
    const int row0 = rg * 4;
    const int c08 = cg * 8;
    const int c04 = cg * 4;

    // --- stage 1: x1 = relu(hs @ Wn1 + b1) -> sX ---
    {
        float acc[4][8];
        gemm_acc8<64, 64>(sA, sW, row0, c08, acc);
#pragma unroll
        for (int r = 0; r < 4; ++r)
#pragma unroll
            for (int c = 0; c < 8; ++c)
                sX[(row0 + r) * 128 + c08 + c] = fmaxf(acc[r][c] + sB[c08 + c], 0.f);
    }
    __syncthreads();

    // --- stage 2: m1 = x1 @ Wn2 -> sM ---
    load_w(sW, Wn2, 128 * 128, tid);
    __syncthreads();
    {
        float acc[4][8];
        gemm_acc8<128, 128>(sX, sW, row0, c08, acc);
#pragma unroll
        for (int r = 0; r < 4; ++r)
#pragma unroll
            for (int c = 0; c < 8; ++c)
                sM[(row0 + r) * 128 + c08 + c] = acc[r][c];
    }
    __syncthreads();

    // --- stage 3: eh_new = 0.8*eh + 0.2*(t @ Wue) -> sA (hs dead now) ---
    load_w(sW, Wue, 64 * 64, tid);
    __syncthreads();
    {
        float acc[4][4];
        gemm_acc4<64, 64>(sT, sW, row0, c04, acc);
#pragma unroll
        for (int r = 0; r < 4; ++r) {
            int eg = e0 + row0 + r;
            if (eg >= E) eg = E - 1;
            float4 ev = *(const float4*)(eh + (size_t)eg * 64 + c04);
            sA[(row0 + r) * 64 + c04 + 0] = 0.8f * ev.x + 0.2f * acc[r][0];
            sA[(row0 + r) * 64 + c04 + 1] = 0.8f * ev.y + 0.2f * acc[r][1];
            sA[(row0 + r) * 64 + c04 + 2] = 0.8f * ev.z + 0.2f * acc[r][2];
            sA[(row0 + r) * 64 + c04 + 3] = 0.8f * ev.w + 0.2f * acc[r][3];
        }
    }
    __syncthreads();

    // --- stage 4: x2 = relu(eh_new @ We1 + b2) -> sX (x1 dead) ---
    load_w(sW, We1, 64 * 128, tid);
    if (tid < 128) sB[tid] = be1[tid];
    __syncthreads();
    {
        float acc[4][8];
        gemm_acc8<64, 64>(sA, sW, row0, c08, acc);
#pragma unroll
        for (int r = 0; r < 4; ++r)
#pragma unroll
            for (int c = 0; c < 8; ++c)
                sX[(row0 + r) * 128 + c08 + c] = fmaxf(acc[r][c] + sB[c08 + c], 0.f);
    }
    __syncthreads();

    // --- stage 5: p = m1 * (x2 @ We2) -> sM (elementwise, thread owns its tile) ---
    load_w(sW, We2, 128 * 128, tid);
    __syncthreads();
    {
        float acc[4][8];
        gemm_acc8<128, 128>(sX, sW, row0, c08, acc);
#pragma unroll
        for (int r = 0; r < 4; ++r)
#pragma unroll
            for (int c = 0; c < 8; ++c)
                sM[(row0 + r) * 128 + c08 + c] *= acc[r][c];
    }
    __syncthreads();

    // --- stage 6: m = tanh(p @ Wc); scatter-add to out[dst] ---
    load_w(sW, Wc, 128 * 64, tid);
    __syncthreads();
    {
        float acc[4][4];
        gemm_acc4<128, 128>(sM, sW, row0, c04, acc);
#pragma unroll
        for (int r = 0; r < 4; ++r) {
            int eg = e0 + row0 + r;
            if (eg < E) {
                float* base = out + (size_t)sDst[row0 + r] * 64 + c04;
#pragma unroll
                for (int c = 0; c < 4; ++c)
                    atomicAdd(base + c, tanhf(acc[r][c]));
            }
        }
    }
}

extern "C" void kernel_launch(void* const* d_in, const int* in_sizes, int n_in,
                              void* d_out, int out_size) {
    const float* h   = (const float*)d_in[0];
    const float* eh  = (const float*)d_in[1];
    const float* Wn1 = (const float*)d_in[2];
    const float* bn1 = (const float*)d_in[3];
    const float* Wn2 = (const float*)d_in[4];
    const float* We1 = (const float*)d_in[5];
    const float* be1 = (const float*)d_in[6];
    const float* We2 = (const float*)d_in[7];
    const float* Wc  = (const float*)d_in[8];
    const float* Wue = (const float*)d_in[9];
    const int*   src = (const int*)d_in[10];
    const int*   dst = (const int*)d_in[11];
    float* out = (float*)d_out;

    int E = in_sizes[10];
    int n4 = out_size / 4;

    cudaFuncSetAttribute(edge_kernel, cudaFuncAttributeMaxDynamicSharedMemorySize, SMEM_BYTES);

    int init_blocks = (n4 + 255) / 256;
    if (init_blocks > 3125) init_blocks = 3125;
    init_out<<<init_blocks, 256>>>((const float4*)h, (float4*)out, n4);

    int blocks = (E + T_EDGES - 1) / T_EDGES;
    edge_kernel<<<blocks, THREADS, SMEM_BYTES>>>(h, eh, Wn1, bn1, Wn2, We1, be1, We2,
                                                 Wc, Wue, src, dst, out, E);
}

// round 3
// speedup vs baseline: 1.5020x; 1.5020x over previous
#include <cuda_runtime.h>
#include <cuda_bf16.h>
#include <mma.h>
#include <math.h>

using namespace nvcuda;

#define THREADS 256
#define M_TILE 128   // edges per block

// ---- converted bf16 weights live in a device global (no allocs allowed) ----
// segments (element offsets): Wn1[64x128]@0, Wn2[128x128]@8192, Wue[64x64]@24576,
// We1[64x128]@28672, We2[128x128]@36864, Wc[128x64]@53248  -> total 61440
#define OFF_WN1 0
#define OFF_WN2 8192
#define OFF_WUE 24576
#define OFF_WE1 28672
#define OFF_WE2 36864
#define OFF_WC  53248
#define W_TOTAL 61440
__device__ __align__(16) __nv_bfloat16 g_wbuf[W_TOTAL];

__global__ void convert_weights(const float* __restrict__ Wn1, const float* __restrict__ Wn2,
                                const float* __restrict__ Wue, const float* __restrict__ We1,
                                const float* __restrict__ We2, const float* __restrict__ Wc) {
    int i = blockIdx.x * blockDim.x + threadIdx.x;
    if (i >= W_TOTAL) return;
    float v;
    if      (i < OFF_WN2) v = Wn1[i - OFF_WN1];
    else if (i < OFF_WUE) v = Wn2[i - OFF_WN2];
    else if (i < OFF_WE1) v = Wue[i - OFF_WUE];
    else if (i < OFF_WE2) v = We1[i - OFF_WE1];
    else if (i < OFF_WC)  v = We2[i - OFF_WE2];
    else                  v = Wc[i - OFF_WC];
    g_wbuf[i] = __float2bfloat16(v);
}

__global__ void init_out(const float4* __restrict__ h4, float4* __restrict__ o4, int n4) {
    int i = blockIdx.x * blockDim.x + threadIdx.x;
    int stride = gridDim.x * blockDim.x;
    for (int j = i; j < n4; j += stride) o4[j] = h4[j];
}

// Shared memory layout (bytes, 16B aligned):
//  sC   : 128*128 f32  = 65536   (fp32 accumulator staging)
//  sW   : 128*128 bf16 = 32768   (staged weight)
//  sX   : 128*128 bf16 = 32768   (x1 / x2 / p)
//  sM1  : 128*128 bf16 = 32768   (m1)
//  sHS  : 128*64  bf16 = 16384   (hs, later eh_new)
//  sT   : 128*64  bf16 = 16384   (t = hs*hd)
//  sB   : 128 f32      = 512
//  sSrc : 128 int      = 512
//  sDst : 128 int      = 512
#define SMEM_BYTES (65536 + 32768*3 + 16384*2 + 512*3)

__device__ __forceinline__ void load_wbf(__nv_bfloat16* s, const __nv_bfloat16* g, int n, int tid) {
    const uint4* g4 = (const uint4*)g;
    uint4* s4 = (uint4*)s;
    int n8 = n >> 3;
    for (int i = tid; i < n8; i += THREADS) s4[i] = g4[i];
}

__device__ __forceinline__ uint2 pack4_bf16(float a, float b, float c, float d) {
    __nv_bfloat162 lo = __float22bfloat162_rn(make_float2(a, b));
    __nv_bfloat162 hi = __float22bfloat162_rn(make_float2(c, d));
    uint2 r;
    r.x = *(unsigned int*)&lo;
    r.y = *(unsigned int*)&hi;
    return r;
}

// One warp computes a 16 x (NT*16) strip:  C[m0:m0+16, :] = A[m0:m0+16, 0:KT*16] @ W
template<int KT, int NT>
__device__ __forceinline__ void stage_mma(const __nv_bfloat16* sA, const __nv_bfloat16* sWl,
                                          float* sC, int warp) {
    constexpr int ldA = KT * 16;
    constexpr int ldB = NT * 16;
    constexpr int ldC = NT * 16;
    const int m0 = warp * 16;
    wmma::fragment<wmma::matrix_a, 16, 16, 16, __nv_bfloat16, wmma::row_major> a[KT];
#pragma unroll
    for (int k = 0; k < KT; ++k)
        wmma::load_matrix_sync(a[k], sA + m0 * ldA + k * 16, ldA);
#pragma unroll
    for (int n = 0; n < NT; ++n) {
        wmma::fragment<wmma::accumulator, 16, 16, 16, float> c;
        wmma::fill_fragment(c, 0.0f);
#pragma unroll
        for (int k = 0; k < KT; ++k) {
            wmma::fragment<wmma::matrix_b, 16, 16, 16, __nv_bfloat16, wmma::row_major> b;
            wmma::load_matrix_sync(b, sWl + k * 16 * ldB + n * 16, ldB);
            wmma::mma_sync(c, a[k], b, c);
        }
        wmma::store_matrix_sync(sC + m0 * ldC + n * 16, c, ldC, wmma::mem_row_major);
    }
}

__global__ __launch_bounds__(THREADS, 1)
void edge_kernel(const float* __restrict__ h, const float* __restrict__ eh,
                 const float* __restrict__ bn1, const float* __restrict__ be1,
                 const int* __restrict__ src, const int* __restrict__ dst,
                 float* __restrict__ out, int E)
{
    extern __shared__ char smem[];
    float*        sC   = (float*)smem;                       // 65536
    __nv_bfloat16* sW  = (__nv_bfloat16*)(smem + 65536);     // 32768
    __nv_bfloat16* sX  = (__nv_bfloat16*)(smem + 98304);     // 32768
    __nv_bfloat16* sM1 = (__nv_bfloat16*)(smem + 131072);    // 32768
    __nv_bfloat16* sHS = (__nv_bfloat16*)(smem + 163840);    // 16384
    __nv_bfloat16* sT  = (__nv_bfloat16*)(smem + 180224);    // 16384
    float*        sB   = (float*)(smem + 196608);            // 512
    int*          sSrc = (int*)(smem + 197120);              // 512
    int*          sDst = (int*)(smem + 197632);              // 512

    const int tid = threadIdx.x;
    const int warp = tid >> 5;
    const int e0 = blockIdx.x * M_TILE;

    // ---- indices ----
    if (tid < M_TILE) {
        int eg = e0 + tid;
        if (eg >= E) eg = E - 1;
        sSrc[tid] = src[eg];
        sDst[tid] = dst[eg];
    }
    __syncthreads();

    // ---- gather: hs -> sHS (bf16), t = hs*hd -> sT (bf16); stage Wn1 + b1 ----
    for (int i = tid; i < M_TILE * 16; i += THREADS) {
        int e = i >> 4;
        int d4 = i & 15;
        float4 a = ((const float4*)(h + (size_t)sSrc[e] * 64))[d4];
        float4 b = ((const float4*)(h + (size_t)sDst[e] * 64))[d4];
        ((uint2*)(sHS + e * 64))[d4] = pack4_bf16(a.x, a.y, a.z, a.w);
        ((uint2*)(sT + e * 64))[d4]  = pack4_bf16(a.x * b.x, a.y * b.y, a.z * b.z, a.w * b.w);
    }
    load_wbf(sW, g_wbuf + OFF_WN1, 64 * 128, tid);
    if (tid < 128) sB[tid] = bn1[tid];
    __syncthreads();

    // ---- stage 1: x1 = relu(hs @ Wn1 + b1) -> sX ----
    stage_mma<4, 8>(sHS, sW, sC, warp);
    __syncthreads();
    for (int i = tid; i < 128 * 32; i += THREADS) {      // 4096 float4 groups
        int r = i >> 5, c = (i & 31) << 2;
        float4 v = *(const float4*)(sC + r * 128 + c);
        float4 bb = *(const float4*)(sB + c);
        *(uint2*)(sX + r * 128 + c) = pack4_bf16(
            fmaxf(v.x + bb.x, 0.f), fmaxf(v.y + bb.y, 0.f),
            fmaxf(v.z + bb.z, 0.f), fmaxf(v.w + bb.w, 0.f));
    }
    __syncthreads();

    // ---- stage 2: m1 = x1 @ Wn2 -> sM1 ----
    load_wbf(sW, g_wbuf + OFF_WN2, 128 * 128, tid);
    __syncthreads();
    stage_mma<8, 8>(sX, sW, sC, warp);
    __syncthreads();
    for (int i = tid; i < 128 * 32; i += THREADS) {
        int r = i >> 5, c = (i & 31) << 2;
        float4 v = *(const float4*)(sC + r * 128 + c);
        *(uint2*)(sM1 + r * 128 + c) = pack4_bf16(v.x, v.y, v.z, v.w);
    }
    __syncthreads();

    // ---- stage 3: eh_new = 0.8*eh + 0.2*(t @ Wue) -> sHS (hs dead) ----
    load_wbf(sW, g_wbuf + OFF_WUE, 64 * 64, tid);
    __syncthreads();
    stage_mma<4, 4>(sT, sW, sC, warp);
    __syncthreads();
    for (int i = tid; i < 128 * 16; i += THREADS) {      // 2048 float4 groups
        int r = i >> 4, c = (i & 15) << 2;
        int eg = e0 + r; if (eg >= E) eg = E - 1;
        float4 v = *(const float4*)(sC + r * 64 + c);
        float4 ev = *(const float4*)(eh + (size_t)eg * 64 + c);
        *(uint2*)(sHS + r * 64 + c) = pack4_bf16(
            0.8f * ev.x + 0.2f * v.x, 0.8f * ev.y + 0.2f * v.y,
            0.8f * ev.z + 0.2f * v.z, 0.8f * ev.w + 0.2f * v.w);
    }
    __syncthreads();

    // ---- stage 4: x2 = relu(eh_new @ We1 + b2) -> sX ----
    load_wbf(sW, g_wbuf + OFF_WE1, 64 * 128, tid);
    if (tid < 128) sB[tid] = be1[tid];
    __syncthreads();
    stage_mma<4, 8>(sHS, sW, sC, warp);
    __syncthreads();
    for (int i = tid; i < 128 * 32; i += THREADS) {
        int r = i >> 5, c = (i & 31) << 2;
        float4 v = *(const float4*)(sC + r * 128 + c);
        float4 bb = *(const float4*)(sB + c);
        *(uint2*)(sX + r * 128 + c) = pack4_bf16(
            fmaxf(v.x + bb.x, 0.f), fmaxf(v.y + bb.y, 0.f),
            fmaxf(v.z + bb.z, 0.f), fmaxf(v.w + bb.w, 0.f));
    }
    __syncthreads();

    // ---- stage 5: p = m1 * (x2 @ We2) -> sX ----
    load_wbf(sW, g_wbuf + OFF_WE2, 128 * 128, tid);
    __syncthreads();
    stage_mma<8, 8>(sX, sW, sC, warp);
    __syncthreads();
    for (int i = tid; i < 128 * 32; i += THREADS) {
        int r = i >> 5, c = (i & 31) << 2;
        float4 v = *(const float4*)(sC + r * 128 + c);
        uint2 m1p = *(const uint2*)(sM1 + r * 128 + c);
        __nv_bfloat162 m1lo = *(__nv_bfloat162*)&m1p.x;
        __nv_bfloat162 m1hi = *(__nv_bfloat162*)&m1p.y;
        *(uint2*)(sX + r * 128 + c) = pack4_bf16(
            v.x * __bfloat162float(m1lo.x), v.y * __bfloat162float(m1lo.y),
            v.z * __bfloat162float(m1hi.x), v.w * __bfloat162float(m1hi.y));
    }
    __syncthreads();

    // ---- stage 6: m = tanh(p @ Wc); scatter-add ----
    load_wbf(sW, g_wbuf + OFF_WC, 128 * 64, tid);
    __syncthreads();
    stage_mma<8, 4>(sX, sW, sC, warp);
    __syncthreads();
    for (int i = tid; i < 128 * 16; i += THREADS) {
        int r = i >> 4, c = (i & 15) << 2;
        int eg = e0 + r;
        if (eg < E) {
            float4 v = *(const float4*)(sC + r * 64 + c);
            float* base = out + (size_t)sDst[r] * 64 + c;
            atomicAdd(base + 0, tanhf(v.x));
            atomicAdd(base + 1, tanhf(v.y));
            atomicAdd(base + 2, tanhf(v.z));
            atomicAdd(base + 3, tanhf(v.w));
        }
    }
}

extern "C" void kernel_launch(void* const* d_in, const int* in_sizes, int n_in,
                              void* d_out, int out_size) {
    const float* h   = (const float*)d_in[0];
    const float* eh  = (const float*)d_in[1];
    const float* Wn1 = (const float*)d_in[2];
    const float* bn1 = (const float*)d_in[3];
    const float* Wn2 = (const float*)d_in[4];
    const float* We1 = (const float*)d_in[5];
    const float* be1 = (const float*)d_in[6];
    const float* We2 = (const float*)d_in[7];
    const float* Wc  = (const float*)d_in[8];
    const float* Wue = (const float*)d_in[9];
    const int*   src = (const int*)d_in[10];
    const int*   dst = (const int*)d_in[11];
    float* out = (float*)d_out;

    int E = in_sizes[10];
    int n4 = out_size / 4;

    convert_weights<<<(W_TOTAL + 255) / 256, 256>>>(Wn1, Wn2, Wue, We1, We2, Wc);

    int init_blocks = (n4 + 255) / 256;
    if (init_blocks > 3125) init_blocks = 3125;
    init_out<<<init_blocks, 256>>>((const float4*)h, (float4*)out, n4);

    cudaFuncSetAttribute(edge_kernel, cudaFuncAttributeMaxDynamicSharedMemorySize, SMEM_BYTES);
    int blocks = (E + M_TILE - 1) / M_TILE;
    edge_kernel<<<blocks, THREADS, SMEM_BYTES>>>(h, eh, bn1, be1, src, dst, out, E);
}

// round 5
// speedup vs baseline: 8.1550x; 5.4295x over previous
#include <cuda_runtime.h>
#include <cuda_bf16.h>
#include <math.h>
#include <stdint.h>

#define THREADS 256
#define M_TILE 128   // edges per tile

// Padded row strides (bytes) -> conflict-free ldmatrix
#define STRIDE128 272   // 128 bf16 + 16B pad
#define STRIDE64  144   // 64 bf16 + 16B pad

// ---- smem layout (bytes) ----
#define W1_OFF  0                          // Wn1 [64 x128]  17408
#define W2_OFF  (W1_OFF + 64*STRIDE128)    // Wn2 [128x128]  34816
#define WU_OFF  (W2_OFF + 128*STRIDE128)   // Wue [64 x64]    9216
#define W3_OFF  (WU_OFF + 64*STRIDE64)     // We1 [64 x128]  17408
#define W4_OFF  (W3_OFF + 64*STRIDE128)    // We2 [128x128]  34816
#define W5_OFF  (W4_OFF + 128*STRIDE128)   // Wc  [128x64]   18432
#define SHS_OFF (W5_OFF + 128*STRIDE64)    // hs / eh_new [128x64]
#define ST_OFF  (SHS_OFF + 128*STRIDE64)   // t = hs*hd   [128x64]
#define SX_OFF  (ST_OFF + 128*STRIDE64)    // x1/x2/p     [128x128]
#define SB1_OFF (SX_OFF + 128*STRIDE128)
#define SB2_OFF (SB1_OFF + 512)
#define SSRC_OFF (SB2_OFF + 512)
#define SDST_OFF (SSRC_OFF + 512)
#define SMEM_BYTES (SDST_OFF + 512)        // = 205824 (< 227KB)

__global__ void init_out(const float4* __restrict__ h4, float4* __restrict__ o4, int n4) {
    int i = blockIdx.x * blockDim.x + threadIdx.x;
    int stride = gridDim.x * blockDim.x;
    for (int j = i; j < n4; j += stride) o4[j] = h4[j];
}

__device__ __forceinline__ uint32_t smem_u32(const void* p) {
    uint32_t a;
    asm("{ .reg .u64 t; cvta.to.shared.u64 t, %1; cvt.u32.u64 %0, t; }" : "=r"(a) : "l"(p));
    return a;
}

__device__ __forceinline__ uint32_t pack2_bf16(float a, float b) {
    __nv_bfloat162 p = __float22bfloat162_rn(make_float2(a, b));
    return *(unsigned int*)&p;
}
__device__ __forceinline__ uint2 pack4_bf16(float a, float b, float c, float d) {
    uint2 r; r.x = pack2_bf16(a, b); r.y = pack2_bf16(c, d); return r;
}

__device__ __forceinline__ void ldsm_x4(uint32_t addr, uint32_t r[4]) {
    asm volatile("ldmatrix.sync.aligned.m8n8.x4.shared.b16 {%0,%1,%2,%3}, [%4];"
        : "=r"(r[0]), "=r"(r[1]), "=r"(r[2]), "=r"(r[3]) : "r"(addr));
}
__device__ __forceinline__ void ldsm_x2t(uint32_t addr, uint32_t r[2]) {
    asm volatile("ldmatrix.sync.aligned.m8n8.x2.trans.shared.b16 {%0,%1}, [%2];"
        : "=r"(r[0]), "=r"(r[1]) : "r"(addr));
}
__device__ __forceinline__ void mma16816(float d[4], const uint32_t a[4], const uint32_t b[2]) {
    asm volatile("mma.sync.aligned.m16n8k16.row.col.f32.bf16.bf16.f32 "
        "{%0,%1,%2,%3},{%4,%5,%6,%7},{%8,%9},{%0,%1,%2,%3};"
        : "+f"(d[0]), "+f"(d[1]), "+f"(d[2]), "+f"(d[3])
        : "r"(a[0]), "r"(a[1]), "r"(a[2]), "r"(a[3]), "r"(b[0]), "r"(b[1]));
}

// acc[mt][n][4] = A[m0+mt*16 .. +15, 0:KT*16] @ W[:, n0+n*8 .. +7]
template<int KT, int NTH>
__device__ __forceinline__ void mma_stage(uint32_t aAddr, int aStride,
                                          uint32_t wAddr, int wStride,
                                          int m0, int n0, int lane,
                                          float acc[2][NTH][4]) {
#pragma unroll
    for (int mt = 0; mt < 2; ++mt)
#pragma unroll
        for (int n = 0; n < NTH; ++n)
#pragma unroll
            for (int e = 0; e < 4; ++e) acc[mt][n][e] = 0.f;

    const int arow = (lane & 15);
    const int acol = (lane >> 4) << 3;
    const int brow = (lane & 15);
#pragma unroll
    for (int k = 0; k < KT; ++k) {
        uint32_t a[2][4];
#pragma unroll
        for (int mt = 0; mt < 2; ++mt)
            ldsm_x4(aAddr + (uint32_t)(m0 + mt * 16 + arow) * aStride + (uint32_t)(k * 16 + acol) * 2,
                    a[mt]);
#pragma unroll
        for (int n = 0; n < NTH; ++n) {
            uint32_t b[2];
            ldsm_x2t(wAddr + (uint32_t)(k * 16 + brow) * wStride + (uint32_t)(n0 + n * 8) * 2, b[0 ? 0 : 0] == 0 ? b : b); // placate nothing
            ldsm_x2t(wAddr + (uint32_t)(k * 16 + brow) * wStride + (uint32_t)(n0 + n * 8) * 2, b);
            mma16816(acc[0][n], a[0], b);
            mma16816(acc[1][n], a[1], b);
        }
    }
}

// load fp32 [K,N] row-major weight -> padded bf16 smem tile
__device__ __forceinline__ void load_weight(char* smemc, int off, const float* __restrict__ W,
                                            int K, int N, int stride, int tid) {
    int n4 = (K * N) >> 2;
    for (int i = tid; i < n4; i += THREADS) {
        int idx = i << 2;
        int r = idx / N, c = idx % N;
        float4 v = *(const float4*)(W + idx);
        *(uint2*)(smemc + off + r * stride + c * 2) = pack4_bf16(v.x, v.y, v.z, v.w);
    }
}

__global__ __launch_bounds__(THREADS)
void edge_kernel(const float* __restrict__ h, const float* __restrict__ eh,
                 const float* __restrict__ Wn1, const float* __restrict__ bn1,
                 const float* __restrict__ Wn2,
                 const float* __restrict__ We1, const float* __restrict__ be1,
                 const float* __restrict__ We2,
                 const float* __restrict__ Wc, const float* __restrict__ Wue,
                 const int* __restrict__ src, const int* __restrict__ dst,
                 float* __restrict__ out, int E, int nTiles)
{
    extern __shared__ char smem[];
    const uint32_t sbase = smem_u32(smem);
    const int tid = threadIdx.x;
    const int warp = tid >> 5;
    const int lane = tid & 31;

    // warp tiling: 4 M-strips x 2 N-halves
    const int mi = warp >> 1;
    const int nj = warp & 1;
    const int m0 = mi * 32;
    const int n0w = nj * 64;  // N=128 stages
    const int n0h = nj * 32;  // N=64 stages

    float* sB1 = (float*)(smem + SB1_OFF);
    float* sB2 = (float*)(smem + SB2_OFF);
    int* sSrc = (int*)(smem + SSRC_OFF);
    int* sDst = (int*)(smem + SDST_OFF);

    // ---- one-time: stage all weights + biases into smem ----
    load_weight(smem, W1_OFF, Wn1, 64, 128, STRIDE128, tid);
    load_weight(smem, W2_OFF, Wn2, 128, 128, STRIDE128, tid);
    load_weight(smem, WU_OFF, Wue, 64, 64, STRIDE64, tid);
    load_weight(smem, W3_OFF, We1, 64, 128, STRIDE128, tid);
    load_weight(smem, W4_OFF, We2, 128, 128, STRIDE128, tid);
    load_weight(smem, W5_OFF, Wc, 128, 64, STRIDE64, tid);
    if (tid < 128) { sB1[tid] = bn1[tid]; sB2[tid] = be1[tid]; }
    __syncthreads();

    const int g = lane >> 2;       // row-in-group 0..7
    const int q = lane & 3;        // col pair selector

    for (int tile = blockIdx.x; tile < nTiles; tile += gridDim.x) {
        const int e0 = tile * M_TILE;
        __syncthreads();  // protect smem reused from previous iteration

        if (tid < M_TILE) {
            int eg = e0 + tid;
            if (eg >= E) eg = E - 1;
            sSrc[tid] = src[eg];
            sDst[tid] = dst[eg];
        }
        __syncthreads();

        // gather: hs -> SHS, t = hs*hd -> ST (padded bf16 rows)
        for (int i = tid; i < M_TILE * 16; i += THREADS) {
            int e = i >> 4, d4 = i & 15;
            float4 a = ((const float4*)(h + (size_t)sSrc[e] * 64))[d4];
            float4 b = ((const float4*)(h + (size_t)sDst[e] * 64))[d4];
            *(uint2*)(smem + SHS_OFF + e * STRIDE64 + d4 * 8) = pack4_bf16(a.x, a.y, a.z, a.w);
            *(uint2*)(smem + ST_OFF + e * STRIDE64 + d4 * 8) =
                pack4_bf16(a.x * b.x, a.y * b.y, a.z * b.z, a.w * b.w);
        }
        __syncthreads();

        float acc[2][8][4];
        float m1[2][8][4];

        // ---- stage 1: x1 = relu(hs @ Wn1 + b1) -> SX ----
        mma_stage<4, 8>(sbase + SHS_OFF, STRIDE64, sbase + W1_OFF, STRIDE128, m0, n0w, lane, acc);
#pragma unroll
        for (int mt = 0; mt < 2; ++mt)
#pragma unroll
            for (int n = 0; n < 8; ++n) {
                int col = n0w + n * 8 + q * 2;
                float b0 = sB1[col], b1 = sB1[col + 1];
                int rA = m0 + mt * 16 + g;
                *(uint32_t*)(smem + SX_OFF + rA * STRIDE128 + col * 2) =
                    pack2_bf16(fmaxf(acc[mt][n][0] + b0, 0.f), fmaxf(acc[mt][n][1] + b1, 0.f));
                *(uint32_t*)(smem + SX_OFF + (rA + 8) * STRIDE128 + col * 2) =
                    pack2_bf16(fmaxf(acc[mt][n][2] + b0, 0.f), fmaxf(acc[mt][n][3] + b1, 0.f));
            }
        __syncthreads();

        // ---- stage 2: m1 = x1 @ Wn2 (kept in registers, fp32) ----
        mma_stage<8, 8>(sbase + SX_OFF, STRIDE128, sbase + W2_OFF, STRIDE128, m0, n0w, lane, m1);

        // ---- stage 3: eh_new = 0.8*eh + 0.2*(t @ Wue) -> SHS ----
        mma_stage<4, 4>(sbase + ST_OFF, STRIDE64, sbase + WU_OFF, STRIDE64, m0, n0h, lane,
                        *(float(*)[2][4][4])&acc[0][0][0]);
        {
            float(&a3)[2][4][4] = *(float(*)[2][4][4])&acc[0][0][0];
#pragma unroll
            for (int mt = 0; mt < 2; ++mt)
#pragma unroll
                for (int n = 0; n < 4; ++n) {
                    int col = n0h + n * 8 + q * 2;
                    int rA = m0 + mt * 16 + g;
                    int egA = e0 + rA; if (egA >= E) egA = E - 1;
                    int egB = e0 + rA + 8; if (egB >= E) egB = E - 1;
                    float2 evA = *(const float2*)(eh + (size_t)egA * 64 + col);
                    float2 evB = *(const float2*)(eh + (size_t)egB * 64 + col);
                    *(uint32_t*)(smem + SHS_OFF + rA * STRIDE64 + col * 2) =
                        pack2_bf16(0.8f * evA.x + 0.2f * a3[mt][n][0],
                                   0.8f * evA.y + 0.2f * a3[mt][n][1]);
                    *(uint32_t*)(smem + SHS_OFF + (rA + 8) * STRIDE64 + col * 2) =
                        pack2_bf16(0.8f * evB.x + 0.2f * a3[mt][n][2],
                                   0.8f * evB.y + 0.2f * a3[mt][n][3]);
                }
        }
        __syncthreads();

        // ---- stage 4: x2 = relu(eh_new @ We1 + b2) -> SX ----
        mma_stage<4, 8>(sbase + SHS_OFF, STRIDE64, sbase + W3_OFF, STRIDE128, m0, n0w, lane, acc);
#pragma unroll
        for (int mt = 0; mt < 2; ++mt)
#pragma unroll
            for (int n = 0; n < 8; ++n) {
                int col = n0w + n * 8 + q * 2;
                float b0 = sB2[col], b1 = sB2[col + 1];
                int rA = m0 + mt * 16 + g;
                *(uint32_t*)(smem + SX_OFF + rA * STRIDE128 + col * 2) =
                    pack2_bf16(fmaxf(acc[mt][n][0] + b0, 0.f), fmaxf(acc[mt][n][1] + b1, 0.f));
                *(uint32_t*)(smem + SX_OFF + (rA + 8) * STRIDE128 + col * 2) =
                    pack2_bf16(fmaxf(acc[mt][n][2] + b0, 0.f), fmaxf(acc[mt][n][3] + b1, 0.f));
            }
        __syncthreads();

        // ---- stage 5: p = m1 * (x2 @ We2) -> SX (in place; sync around write) ----
        mma_stage<8, 8>(sbase + SX_OFF, STRIDE128, sbase + W4_OFF, STRIDE128, m0, n0w, lane, acc);
        __syncthreads();
#pragma unroll
        for (int mt = 0; mt < 2; ++mt)
#pragma unroll
            for (int n = 0; n < 8; ++n) {
                int col = n0w + n * 8 + q * 2;
                int rA = m0 + mt * 16 + g;
                *(uint32_t*)(smem + SX_OFF + rA * STRIDE128 + col * 2) =
                    pack2_bf16(acc[mt][n][0] * m1[mt][n][0], acc[mt][n][1] * m1[mt][n][1]);
                *(uint32_t*)(smem + SX_OFF + (rA + 8) * STRIDE128 + col * 2) =
                    pack2_bf16(acc[mt][n][2] * m1[mt][n][2], acc[mt][n][3] * m1[mt][n][3]);
            }
        __syncthreads();

        // ---- stage 6: m = tanh(p @ Wc); vector reduce-add to out[dst] ----
        mma_stage<8, 4>(sbase + SX_OFF, STRIDE128, sbase + W5_OFF, STRIDE64, m0, n0h, lane,
                        *(float(*)[2][4][4])&acc[0][0][0]);
        {
            float(&a6)[2][4][4] = *(float(*)[2][4][4])&acc[0][0][0];
#pragma unroll
            for (int mt = 0; mt < 2; ++mt) {
                int rA = m0 + mt * 16 + g;
                int egA = e0 + rA, egB = e0 + rA + 8;
                int dA = sDst[rA], dB = sDst[rA + 8];
#pragma unroll
                for (int n = 0; n < 4; ++n) {
                    int col = n0h + n * 8 + q * 2;
                    if (egA < E) {
                        float* p = out + (size_t)dA * 64 + col;
                        asm volatile("red.global.add.v2.f32 [%0], {%1,%2};"
                            :: "l"(p), "f"(tanhf(a6[mt][n][0])), "f"(tanhf(a6[mt][n][1])) : "memory");
                    }
                    if (egB < E) {
                        float* p = out + (size_t)dB * 64 + col;
                        asm volatile("red.global.add.v2.f32 [%0], {%1,%2};"
                            :: "l"(p), "f"(tanhf(a6[mt][n][2])), "f"(tanhf(a6[mt][n][3])) : "memory");
                    }
                }
            }
        }
    }
}

extern "C" void kernel_launch(void* const* d_in, const int* in_sizes, int n_in,
                              void* d_out, int out_size) {
    const float* h   = (const float*)d_in[0];
    const float* eh  = (const float*)d_in[1];
    const float* Wn1 = (const float*)d_in[2];
    const float* bn1 = (const float*)d_in[3];
    const float* Wn2 = (const float*)d_in[4];
    const float* We1 = (const float*)d_in[5];
    const float* be1 = (const float*)d_in[6];
    const float* We2 = (const float*)d_in[7];
    const float* Wc  = (const float*)d_in[8];
    const float* Wue = (const float*)d_in[9];
    const int*   src = (const int*)d_in[10];
    const int*   dst = (const int*)d_in[11];
    float* out = (float*)d_out;

    int E = in_sizes[10];
    int n4 = out_size / 4;
    int nTiles = (E + M_TILE - 1) / M_TILE;

    int init_blocks = (n4 + 255) / 256;
    if (init_blocks > 3125) init_blocks = 3125;
    init_out<<<init_blocks, 256>>>((const float4*)h, (float4*)out, n4);

    int nSM = 148;
    cudaDeviceGetAttribute(&nSM, cudaDevAttrMultiProcessorCount, 0);
    int grid = nSM < nTiles ? nSM : nTiles;

    cudaFuncSetAttribute(edge_kernel, cudaFuncAttributeMaxDynamicSharedMemorySize, SMEM_BYTES);
    edge_kernel<<<grid, THREADS, SMEM_BYTES>>>(h, eh, Wn1, bn1, Wn2, We1, be1, We2,
                                               Wc, Wue, src, dst, out, E, nTiles);
}

// round 6
// speedup vs baseline: 9.3731x; 1.1494x over previous
#include <cuda_runtime.h>
#include <cuda_bf16.h>
#include <math.h>
#include <stdint.h>

#define THREADS 512
#define M_TILE 128   // edges per tile

// Padded row strides (bytes) -> conflict-free ldmatrix
#define STRIDE128 272   // 128 bf16 + 16B pad
#define STRIDE64  144   // 64 bf16 + 16B pad

// ---- smem layout (bytes) ----
#define W1_OFF  0                          // Wn1 [64 x128]  17408
#define W2_OFF  (W1_OFF + 64*STRIDE128)    // Wn2 [128x128]  34816
#define WU_OFF  (W2_OFF + 128*STRIDE128)   // Wue [64 x64]    9216
#define W3_OFF  (WU_OFF + 64*STRIDE64)     // We1 [64 x128]  17408
#define W4_OFF  (W3_OFF + 64*STRIDE128)    // We2 [128x128]  34816
#define W5_OFF  (W4_OFF + 128*STRIDE128)   // Wc  [128x64]   18432
#define SHS_OFF (W5_OFF + 128*STRIDE64)    // hs / eh_new [128x64]
#define ST_OFF  (SHS_OFF + 128*STRIDE64)   // t = hs*hd   [128x64]
#define SX_OFF  (ST_OFF + 128*STRIDE64)    // x1/x2/p     [128x128]
#define SB1_OFF (SX_OFF + 128*STRIDE128)
#define SB2_OFF (SB1_OFF + 512)
#define SSRC_OFF (SB2_OFF + 512)
#define SDST_OFF (SSRC_OFF + 512)
#define SMEM_BYTES (SDST_OFF + 512)        // = 205824 (< 227KB)

__global__ void init_out(const float4* __restrict__ h4, float4* __restrict__ o4, int n4) {
    int i = blockIdx.x * blockDim.x + threadIdx.x;
    int stride = gridDim.x * blockDim.x;
    for (int j = i; j < n4; j += stride) o4[j] = h4[j];
}

__device__ __forceinline__ uint32_t smem_u32(const void* p) {
    uint32_t a;
    asm("{ .reg .u64 t; cvta.to.shared.u64 t, %1; cvt.u32.u64 %0, t; }" : "=r"(a) : "l"(p));
    return a;
}

__device__ __forceinline__ uint32_t pack2_bf16(float a, float b) {
    __nv_bfloat162 p = __float22bfloat162_rn(make_float2(a, b));
    return *(unsigned int*)&p;
}
__device__ __forceinline__ uint2 pack4_bf16(float a, float b, float c, float d) {
    uint2 r; r.x = pack2_bf16(a, b); r.y = pack2_bf16(c, d); return r;
}

__device__ __forceinline__ void ldsm_x4(uint32_t addr, uint32_t r[4]) {
    asm volatile("ldmatrix.sync.aligned.m8n8.x4.shared.b16 {%0,%1,%2,%3}, [%4];"
        : "=r"(r[0]), "=r"(r[1]), "=r"(r[2]), "=r"(r[3]) : "r"(addr));
}
// x4 trans: covers k16 x n16 -> {r0,r1} = B frag for col-tile n, {r2,r3} = col-tile n+8
__device__ __forceinline__ void ldsm_x4t(uint32_t addr, uint32_t r[4]) {
    asm volatile("ldmatrix.sync.aligned.m8n8.x4.trans.shared.b16 {%0,%1,%2,%3}, [%4];"
        : "=r"(r[0]), "=r"(r[1]), "=r"(r[2]), "=r"(r[3]) : "r"(addr));
}
__device__ __forceinline__ void mma16816(float d[4], const uint32_t a[4], const uint32_t b[2]) {
    asm volatile("mma.sync.aligned.m16n8k16.row.col.f32.bf16.bf16.f32 "
        "{%0,%1,%2,%3},{%4,%5,%6,%7},{%8,%9},{%0,%1,%2,%3};"
        : "+f"(d[0]), "+f"(d[1]), "+f"(d[2]), "+f"(d[3])
        : "r"(a[0]), "r"(a[1]), "r"(a[2]), "r"(a[3]), "r"(b[0]), "r"(b[1]));
}

// acc[mt][n][4] = A[m0+mt*16 .. +15, 0:KT*16] @ W[:, n0+n*8 .. +7]; NTH even
template<int KT, int NTH>
__device__ __forceinline__ void mma_stage(uint32_t aAddr, int aStride,
                                          uint32_t wAddr, int wStride,
                                          int m0, int n0, int lane,
                                          float acc[2][NTH][4]) {
#pragma unroll
    for (int mt = 0; mt < 2; ++mt)
#pragma unroll
        for (int n = 0; n < NTH; ++n)
#pragma unroll
            for (int e = 0; e < 4; ++e) acc[mt][n][e] = 0.f;

    const int krow = (lane & 15);
    const int acol = (lane >> 4) << 3;   // A: col offset within k-block
    const int bcol = (lane >> 4) << 3;   // B: n offset selecting the second 8-col tile
#pragma unroll
    for (int k = 0; k < KT; ++k) {
        uint32_t a[2][4];
#pragma unroll
        for (int mt = 0; mt < 2; ++mt)
            ldsm_x4(aAddr + (uint32_t)(m0 + mt * 16 + krow) * aStride + (uint32_t)(k * 16 + acol) * 2,
                    a[mt]);
#pragma unroll
        for (int np = 0; np < NTH / 2; ++np) {
            uint32_t b[4];
            ldsm_x4t(wAddr + (uint32_t)(k * 16 + krow) * wStride
                           + (uint32_t)(n0 + np * 16 + bcol) * 2, b);
            mma16816(acc[0][np * 2 + 0], a[0], b + 0);
            mma16816(acc[1][np * 2 + 0], a[1], b + 0);
            mma16816(acc[0][np * 2 + 1], a[0], b + 2);
            mma16816(acc[1][np * 2 + 1], a[1], b + 2);
        }
    }
}

// load fp32 [K,N] row-major weight -> padded bf16 smem tile
__device__ __forceinline__ void load_weight(char* smemc, int off, const float* __restrict__ W,
                                            int K, int N, int stride, int tid) {
    int n4 = (K * N) >> 2;
    for (int i = tid; i < n4; i += THREADS) {
        int idx = i << 2;
        int r = idx / N, c = idx % N;
        float4 v = *(const float4*)(W + idx);
        *(uint2*)(smemc + off + r * stride + c * 2) = pack4_bf16(v.x, v.y, v.z, v.w);
    }
}

__global__ __launch_bounds__(THREADS)
void edge_kernel(const float* __restrict__ h, const float* __restrict__ eh,
                 const float* __restrict__ Wn1, const float* __restrict__ bn1,
                 const float* __restrict__ Wn2,
                 const float* __restrict__ We1, const float* __restrict__ be1,
                 const float* __restrict__ We2,
                 const float* __restrict__ Wc, const float* __restrict__ Wue,
                 const int* __restrict__ src, const int* __restrict__ dst,
                 float* __restrict__ out, int E, int nTiles)
{
    extern __shared__ char smem[];
    const uint32_t sbase = smem_u32(smem);
    const int tid = threadIdx.x;
    const int warp = tid >> 5;
    const int lane = tid & 31;

    // warp tiling: 4 M-strips x 4 N-quarters
    const int mi = warp >> 2;
    const int nj = warp & 3;
    const int m0 = mi * 32;
    const int n0w = nj * 32;  // N=128 stages (NTH=4)
    const int n0h = nj * 16;  // N=64 stages  (NTH=2)

    float* sB1 = (float*)(smem + SB1_OFF);
    float* sB2 = (float*)(smem + SB2_OFF);
    int* sSrc = (int*)(smem + SSRC_OFF);
    int* sDst = (int*)(smem + SDST_OFF);

    // ---- one-time: stage all weights + biases into smem ----
    load_weight(smem, W1_OFF, Wn1, 64, 128, STRIDE128, tid);
    load_weight(smem, W2_OFF, Wn2, 128, 128, STRIDE128, tid);
    load_weight(smem, WU_OFF, Wue, 64, 64, STRIDE64, tid);
    load_weight(smem, W3_OFF, We1, 64, 128, STRIDE128, tid);
    load_weight(smem, W4_OFF, We2, 128, 128, STRIDE128, tid);
    load_weight(smem, W5_OFF, Wc, 128, 64, STRIDE64, tid);
    if (tid < 128) { sB1[tid] = bn1[tid]; sB2[tid] = be1[tid]; }
    __syncthreads();

    const int g = lane >> 2;       // row-in-group 0..7
    const int q = lane & 3;        // col pair selector

    for (int tile = blockIdx.x; tile < nTiles; tile += gridDim.x) {
        const int e0 = tile * M_TILE;
        __syncthreads();  // protect smem reused from previous iteration

        if (tid < M_TILE) {
            int eg = e0 + tid;
            if (eg >= E) eg = E - 1;
            sSrc[tid] = src[eg];
            sDst[tid] = dst[eg];
        }
        __syncthreads();

        // gather: hs -> SHS, t = hs*hd -> ST (padded bf16 rows)
        for (int i = tid; i < M_TILE * 16; i += THREADS) {
            int e = i >> 4, d4 = i & 15;
            float4 a = ((const float4*)(h + (size_t)sSrc[e] * 64))[d4];
            float4 b = ((const float4*)(h + (size_t)sDst[e] * 64))[d4];
            *(uint2*)(smem + SHS_OFF + e * STRIDE64 + d4 * 8) = pack4_bf16(a.x, a.y, a.z, a.w);
            *(uint2*)(smem + ST_OFF + e * STRIDE64 + d4 * 8) =
                pack4_bf16(a.x * b.x, a.y * b.y, a.z * b.z, a.w * b.w);
        }
        __syncthreads();

        float acc[2][4][4];
        float m1[2][4][4];

        // ---- stage 1: x1 = relu(hs @ Wn1 + b1) -> SX ----
        mma_stage<4, 4>(sbase + SHS_OFF, STRIDE64, sbase + W1_OFF, STRIDE128, m0, n0w, lane, acc);
#pragma unroll
        for (int mt = 0; mt < 2; ++mt)
#pragma unroll
            for (int n = 0; n < 4; ++n) {
                int col = n0w + n * 8 + q * 2;
                float b0 = sB1[col], b1 = sB1[col + 1];
                int rA = m0 + mt * 16 + g;
                *(uint32_t*)(smem + SX_OFF + rA * STRIDE128 + col * 2) =
                    pack2_bf16(fmaxf(acc[mt][n][0] + b0, 0.f), fmaxf(acc[mt][n][1] + b1, 0.f));
                *(uint32_t*)(smem + SX_OFF + (rA + 8) * STRIDE128 + col * 2) =
                    pack2_bf16(fmaxf(acc[mt][n][2] + b0, 0.f), fmaxf(acc[mt][n][3] + b1, 0.f));
            }
        __syncthreads();

        // ---- stage 2: m1 = x1 @ Wn2 (kept in registers, fp32) ----
        mma_stage<8, 4>(sbase + SX_OFF, STRIDE128, sbase + W2_OFF, STRIDE128, m0, n0w, lane, m1);

        // ---- stage 3: eh_new = 0.8*eh + 0.2*(t @ Wue) -> SHS ----
        {
            float a3[2][2][4];
            mma_stage<4, 2>(sbase + ST_OFF, STRIDE64, sbase + WU_OFF, STRIDE64, m0, n0h, lane, a3);
#pragma unroll
            for (int mt = 0; mt < 2; ++mt)
#pragma unroll
                for (int n = 0; n < 2; ++n) {
                    int col = n0h + n * 8 + q * 2;
                    int rA = m0 + mt * 16 + g;
                    int egA = e0 + rA; if (egA >= E) egA = E - 1;
                    int egB = e0 + rA + 8; if (egB >= E) egB = E - 1;
                    float2 evA = *(const float2*)(eh + (size_t)egA * 64 + col);
                    float2 evB = *(const float2*)(eh + (size_t)egB * 64 + col);
                    *(uint32_t*)(smem + SHS_OFF + rA * STRIDE64 + col * 2) =
                        pack2_bf16(0.8f * evA.x + 0.2f * a3[mt][n][0],
                                   0.8f * evA.y + 0.2f * a3[mt][n][1]);
                    *(uint32_t*)(smem + SHS_OFF + (rA + 8) * STRIDE64 + col * 2) =
                        pack2_bf16(0.8f * evB.x + 0.2f * a3[mt][n][2],
                                   0.8f * evB.y + 0.2f * a3[mt][n][3]);
                }
        }
        __syncthreads();

        // ---- stage 4: x2 = relu(eh_new @ We1 + b2) -> SX ----
        mma_stage<4, 4>(sbase + SHS_OFF, STRIDE64, sbase + W3_OFF, STRIDE128, m0, n0w, lane, acc);
#pragma unroll
        for (int mt = 0; mt < 2; ++mt)
#pragma unroll
            for (int n = 0; n < 4; ++n) {
                int col = n0w + n * 8 + q * 2;
                float b0 = sB2[col], b1 = sB2[col + 1];
                int rA = m0 + mt * 16 + g;
                *(uint32_t*)(smem + SX_OFF + rA * STRIDE128 + col * 2) =
                    pack2_bf16(fmaxf(acc[mt][n][0] + b0, 0.f), fmaxf(acc[mt][n][1] + b1, 0.f));
                *(uint32_t*)(smem + SX_OFF + (rA + 8) * STRIDE128 + col * 2) =
                    pack2_bf16(fmaxf(acc[mt][n][2] + b0, 0.f), fmaxf(acc[mt][n][3] + b1, 0.f));
            }
        __syncthreads();

        // ---- stage 5: p = m1 * (x2 @ We2) -> SX (in place; sync around write) ----
        mma_stage<8, 4>(sbase + SX_OFF, STRIDE128, sbase + W4_OFF, STRIDE128, m0, n0w, lane, acc);
        __syncthreads();
#pragma unroll
        for (int mt = 0; mt < 2; ++mt)
#pragma unroll
            for (int n = 0; n < 4; ++n) {
                int col = n0w + n * 8 + q * 2;
                int rA = m0 + mt * 16 + g;
                *(uint32_t*)(smem + SX_OFF + rA * STRIDE128 + col * 2) =
                    pack2_bf16(acc[mt][n][0] * m1[mt][n][0], acc[mt][n][1] * m1[mt][n][1]);
                *(uint32_t*)(smem + SX_OFF + (rA + 8) * STRIDE128 + col * 2) =
                    pack2_bf16(acc[mt][n][2] * m1[mt][n][2], acc[mt][n][3] * m1[mt][n][3]);
            }
        __syncthreads();

        // ---- stage 6: m = tanh(p @ Wc); vector reduce-add to out[dst] ----
        {
            float a6[2][2][4];
            mma_stage<8, 2>(sbase + SX_OFF, STRIDE128, sbase + W5_OFF, STRIDE64, m0, n0h, lane, a6);
#pragma unroll
            for (int mt = 0; mt < 2; ++mt) {
                int rA = m0 + mt * 16 + g;
                int egA = e0 + rA, egB = e0 + rA + 8;
                int dA = sDst[rA], dB = sDst[rA + 8];
#pragma unroll
                for (int n = 0; n < 2; ++n) {
                    int col = n0h + n * 8 + q * 2;
                    if (egA < E) {
                        float* p = out + (size_t)dA * 64 + col;
                        asm volatile("red.global.add.v2.f32 [%0], {%1,%2};"
                            :: "l"(p), "f"(tanhf(a6[mt][n][0])), "f"(tanhf(a6[mt][n][1])) : "memory");
                    }
                    if (egB < E) {
                        float* p = out + (size_t)dB * 64 + col;
                        asm volatile("red.global.add.v2.f32 [%0], {%1,%2};"
                            :: "l"(p), "f"(tanhf(a6[mt][n][2])), "f"(tanhf(a6[mt][n][3])) : "memory");
                    }
                }
            }
        }
    }
}

extern "C" void kernel_launch(void* const* d_in, const int* in_sizes, int n_in,
                              void* d_out, int out_size) {
    const float* h   = (const float*)d_in[0];
    const float* eh  = (const float*)d_in[1];
    const float* Wn1 = (const float*)d_in[2];
    const float* bn1 = (const float*)d_in[3];
    const float* Wn2 = (const float*)d_in[4];
    const float* We1 = (const float*)d_in[5];
    const float* be1 = (const float*)d_in[6];
    const float* We2 = (const float*)d_in[7];
    const float* Wc  = (const float*)d_in[8];
    const float* Wue = (const float*)d_in[9];
    const int*   src = (const int*)d_in[10];
    const int*   dst = (const int*)d_in[11];
    float* out = (float*)d_out;

    int E = in_sizes[10];
    int n4 = out_size / 4;
    int nTiles = (E + M_TILE - 1) / M_TILE;

    int init_blocks = (n4 + 255) / 256;
    if (init_blocks > 3125) init_blocks = 3125;
    init_out<<<init_blocks, 256>>>((const float4*)h, (float4*)out, n4);

    int nSM = 148;
    cudaDeviceGetAttribute(&nSM, cudaDevAttrMultiProcessorCount, 0);
    int grid = nSM < nTiles ? nSM : nTiles;

    cudaFuncSetAttribute(edge_kernel, cudaFuncAttributeMaxDynamicSharedMemorySize, SMEM_BYTES);
    edge_kernel<<<grid, THREADS, SMEM_BYTES>>>(h, eh, Wn1, bn1, Wn2, We1, be1, We2,
                                               Wc, Wue, src, dst, out, E, nTiles);
}

// round 7
// speedup vs baseline: 9.7157x; 1.0366x over previous
#include <cuda_runtime.h>
#include <cuda_bf16.h>
#include <math.h>
#include <stdint.h>

#define ETHREADS 512
#define NTHREADS 256
#define M_TILE 256   // edges per tile (two 128-row halves share B fragments)
#define N_MAX 50000

// Padded row strides (bytes) -> conflict-free ldmatrix
#define STRIDE128 272
#define STRIDE64  144

// ---- edge kernel smem (bytes) ----
#define WU_OFF  0                        // Wue [64x64]    9216
#define W3_OFF  (WU_OFF + 64*STRIDE64)   // We1 [64x128]  17408
#define W4_OFF  (W3_OFF + 64*STRIDE128)  // We2 [128x128] 34816
#define W5_OFF  (W4_OFF + 128*STRIDE128) // Wc  [128x64]  18432
#define ST_OFF  (W5_OFF + 128*STRIDE64)  // t        [256x64]  36864
#define SE_OFF  (ST_OFF + 256*STRIDE64)  // eh_new   [256x64]  36864
#define SX_OFF  (SE_OFF + 256*STRIDE64)  // x2 / p   [256x128] 69632
#define SB2_OFF (SX_OFF + 256*STRIDE128) // 512
#define SSRC_OFF (SB2_OFF + 512)         // 1024
#define SDST_OFF (SSRC_OFF + 1024)       // 1024
#define ESMEM_BYTES (SDST_OFF + 1024)    // 225792

// ---- node kernel smem ----
#define NW1_OFF 0                          // Wn1 [64x128]  17408
#define NW2_OFF (NW1_OFF + 64*STRIDE128)   // Wn2 [128x128] 34816
#define NH_OFF  (NW2_OFF + 128*STRIDE128)  // h tile [128x64] 18432
#define NX_OFF  (NH_OFF + 128*STRIDE64)    // x1 [128x128]  34816
#define NB_OFF  (NX_OFF + 128*STRIDE128)   // 512
#define NSMEM_BYTES (NB_OFF + 512)         // 105984

// per-node m1 table: Y1 = relu(h@Wn1+b1)@Wn2, bf16 [N_MAX x 128]
__device__ __align__(16) __nv_bfloat16 g_Y1[(size_t)N_MAX * 128];

__global__ void init_out(const float4* __restrict__ h4, float4* __restrict__ o4, int n4) {
    int i = blockIdx.x * blockDim.x + threadIdx.x;
    int stride = gridDim.x * blockDim.x;
    for (int j = i; j < n4; j += stride) o4[j] = h4[j];
}

__device__ __forceinline__ uint32_t smem_u32(const void* p) {
    uint32_t a;
    asm("{ .reg .u64 t; cvta.to.shared.u64 t, %1; cvt.u32.u64 %0, t; }" : "=r"(a) : "l"(p));
    return a;
}
__device__ __forceinline__ uint32_t pack2_bf16(float a, float b) {
    __nv_bfloat162 p = __float22bfloat162_rn(make_float2(a, b));
    return *(unsigned int*)&p;
}
__device__ __forceinline__ uint2 pack4_bf16(float a, float b, float c, float d) {
    uint2 r; r.x = pack2_bf16(a, b); r.y = pack2_bf16(c, d); return r;
}
__device__ __forceinline__ void ldsm_x4(uint32_t addr, uint32_t r[4]) {
    asm volatile("ldmatrix.sync.aligned.m8n8.x4.shared.b16 {%0,%1,%2,%3}, [%4];"
        : "=r"(r[0]), "=r"(r[1]), "=r"(r[2]), "=r"(r[3]) : "r"(addr));
}
__device__ __forceinline__ void ldsm_x4t(uint32_t addr, uint32_t r[4]) {
    asm volatile("ldmatrix.sync.aligned.m8n8.x4.trans.shared.b16 {%0,%1,%2,%3}, [%4];"
        : "=r"(r[0]), "=r"(r[1]), "=r"(r[2]), "=r"(r[3]) : "r"(addr));
}
__device__ __forceinline__ void mma16816(float d[4], const uint32_t a[4], const uint32_t b[2]) {
    asm volatile("mma.sync.aligned.m16n8k16.row.col.f32.bf16.bf16.f32 "
        "{%0,%1,%2,%3},{%4,%5,%6,%7},{%8,%9},{%0,%1,%2,%3};"
        : "+f"(d[0]), "+f"(d[1]), "+f"(d[2]), "+f"(d[3])
        : "r"(a[0]), "r"(a[1]), "r"(a[2]), "r"(a[3]), "r"(b[0]), "r"(b[1]));
}

// single-M version (node kernel): acc[mt][n][4], warp covers 32 rows x NTH*8 cols
template<int KT, int NTH>
__device__ __forceinline__ void mma_stage(uint32_t aAddr, int aStride,
                                          uint32_t wAddr, int wStride,
                                          int m0, int n0, int lane,
                                          float acc[2][NTH][4]) {
#pragma unroll
    for (int mt = 0; mt < 2; ++mt)
#pragma unroll
        for (int n = 0; n < NTH; ++n)
#pragma unroll
            for (int e = 0; e < 4; ++e) acc[mt][n][e] = 0.f;
    const int krow = lane & 15;
    const int xoff = (lane >> 4) << 3;
#pragma unroll
    for (int k = 0; k < KT; ++k) {
        uint32_t a[2][4];
#pragma unroll
        for (int mt = 0; mt < 2; ++mt)
            ldsm_x4(aAddr + (uint32_t)(m0 + mt * 16 + krow) * aStride + (uint32_t)(k * 16 + xoff) * 2, a[mt]);
#pragma unroll
        for (int np = 0; np < NTH / 2; ++np) {
            uint32_t b[4];
            ldsm_x4t(wAddr + (uint32_t)(k * 16 + krow) * wStride + (uint32_t)(n0 + np * 16 + xoff) * 2, b);
            mma16816(acc[0][np * 2 + 0], a[0], b + 0);
            mma16816(acc[1][np * 2 + 0], a[1], b + 0);
            mma16816(acc[0][np * 2 + 1], a[0], b + 2);
            mma16816(acc[1][np * 2 + 1], a[1], b + 2);
        }
    }
}

// two-half version (edge kernel): warp covers 64 rows; B frags reused across halves
template<int KT, int NTH>
__device__ __forceinline__ void mma_stage2(uint32_t aAddr, int aStride,
                                           uint32_t wAddr, int wStride,
                                           int m0, int n0, int lane,
                                           float acc[2][2][NTH][4]) {
#pragma unroll
    for (int hf = 0; hf < 2; ++hf)
#pragma unroll
        for (int mt = 0; mt < 2; ++mt)
#pragma unroll
            for (int n = 0; n < NTH; ++n)
#pragma unroll
                for (int e = 0; e < 4; ++e) acc[hf][mt][n][e] = 0.f;
    const int krow = lane & 15;
    const int xoff = (lane >> 4) << 3;
#pragma unroll
    for (int k = 0; k < KT; ++k) {
        uint32_t b[NTH / 2][4];
#pragma unroll
        for (int np = 0; np < NTH / 2; ++np)
            ldsm_x4t(wAddr + (uint32_t)(k * 16 + krow) * wStride + (uint32_t)(n0 + np * 16 + xoff) * 2, b[np]);
#pragma unroll
        for (int hf = 0; hf < 2; ++hf) {
            uint32_t a[2][4];
#pragma unroll
            for (int mt = 0; mt < 2; ++mt)
                ldsm_x4(aAddr + (uint32_t)(m0 + hf * 32 + mt * 16 + krow) * aStride + (uint32_t)(k * 16 + xoff) * 2, a[mt]);
#pragma unroll
            for (int np = 0; np < NTH / 2; ++np) {
                mma16816(acc[hf][0][np * 2 + 0], a[0], b[np] + 0);
                mma16816(acc[hf][1][np * 2 + 0], a[1], b[np] + 0);
                mma16816(acc[hf][0][np * 2 + 1], a[0], b[np] + 2);
                mma16816(acc[hf][1][np * 2 + 1], a[1], b[np] + 2);
            }
        }
    }
}

// load fp32 [K,N] row-major weight -> padded bf16 smem tile
__device__ __forceinline__ void load_weight(char* smemc, int off, const float* __restrict__ W,
                                            int K, int N, int stride, int tid, int nthr) {
    int n4 = (K * N) >> 2;
    for (int i = tid; i < n4; i += nthr) {
        int idx = i << 2;
        int r = idx / N, c = idx % N;
        float4 v = *(const float4*)(W + idx);
        *(uint2*)(smemc + off + r * stride + c * 2) = pack4_bf16(v.x, v.y, v.z, v.w);
    }
}

// =============== node kernel: Y1 = relu(h@Wn1+b1)@Wn2 (bf16) ===============
__global__ __launch_bounds__(NTHREADS)
void node_kernel(const float* __restrict__ h,
                 const float* __restrict__ Wn1, const float* __restrict__ bn1,
                 const float* __restrict__ Wn2, int Nn)
{
    extern __shared__ char smem[];
    const uint32_t sbase = smem_u32(smem);
    const int tid = threadIdx.x;
    const int warp = tid >> 5;
    const int lane = tid & 31;
    const int mi = warp >> 1;          // 4 M strips of 32
    const int nj = warp & 1;           // 2 N halves of 64
    const int m0 = mi * 32;
    const int n0 = nj * 64;
    const int g = lane >> 2, q = lane & 3;
    const int r0 = blockIdx.x * 128;

    float* sB = (float*)(smem + NB_OFF);
    load_weight(smem, NW1_OFF, Wn1, 64, 128, STRIDE128, tid, NTHREADS);
    load_weight(smem, NW2_OFF, Wn2, 128, 128, STRIDE128, tid, NTHREADS);
    if (tid < 128) sB[tid] = bn1[tid];

    // h rows (contiguous) -> bf16 smem
    for (int i = tid; i < 128 * 16; i += NTHREADS) {
        int r = i >> 4, d4 = i & 15;
        int nr = r0 + r; if (nr >= Nn) nr = Nn - 1;
        float4 v = ((const float4*)(h + (size_t)nr * 64))[d4];
        *(uint2*)(smem + NH_OFF + r * STRIDE64 + d4 * 8) = pack4_bf16(v.x, v.y, v.z, v.w);
    }
    __syncthreads();

    float acc[2][8][4];
    // s1: x1 = relu(h@Wn1+b1)
    mma_stage<4, 8>(sbase + NH_OFF, STRIDE64, sbase + NW1_OFF, STRIDE128, m0, n0, lane, acc);
#pragma unroll
    for (int mt = 0; mt < 2; ++mt)
#pragma unroll
        for (int n = 0; n < 8; ++n) {
            int col = n0 + n * 8 + q * 2;
            float b0 = sB[col], b1 = sB[col + 1];
            int rA = m0 + mt * 16 + g;
            *(uint32_t*)(smem + NX_OFF + rA * STRIDE128 + col * 2) =
                pack2_bf16(fmaxf(acc[mt][n][0] + b0, 0.f), fmaxf(acc[mt][n][1] + b1, 0.f));
            *(uint32_t*)(smem + NX_OFF + (rA + 8) * STRIDE128 + col * 2) =
                pack2_bf16(fmaxf(acc[mt][n][2] + b0, 0.f), fmaxf(acc[mt][n][3] + b1, 0.f));
        }
    __syncthreads();

    // s2: Y1 = x1 @ Wn2 -> global bf16
    mma_stage<8, 8>(sbase + NX_OFF, STRIDE128, sbase + NW2_OFF, STRIDE128, m0, n0, lane, acc);
#pragma unroll
    for (int mt = 0; mt < 2; ++mt)
#pragma unroll
        for (int n = 0; n < 8; ++n) {
            int col = n0 + n * 8 + q * 2;
            int rA = m0 + mt * 16 + g;
            int nrA = r0 + rA, nrB = r0 + rA + 8;
            if (nrA < Nn)
                *(uint32_t*)(g_Y1 + (size_t)nrA * 128 + col) = pack2_bf16(acc[mt][n][0], acc[mt][n][1]);
            if (nrB < Nn)
                *(uint32_t*)(g_Y1 + (size_t)nrB * 128 + col) = pack2_bf16(acc[mt][n][2], acc[mt][n][3]);
        }
}

// =============== edge kernel ===============
__global__ __launch_bounds__(ETHREADS)
void edge_kernel(const float* __restrict__ h, const float* __restrict__ eh,
                 const float* __restrict__ We1, const float* __restrict__ be1,
                 const float* __restrict__ We2,
                 const float* __restrict__ Wc, const float* __restrict__ Wue,
                 const int* __restrict__ src, const int* __restrict__ dst,
                 float* __restrict__ out, int E, int nTiles)
{
    extern __shared__ char smem[];
    const uint32_t sbase = smem_u32(smem);
    const int tid = threadIdx.x;
    const int warp = tid >> 5;
    const int lane = tid & 31;

    // 16 warps: 4 M-strips (64 rows) x 4 N-quarters
    const int mi = warp >> 2;
    const int nj = warp & 3;
    const int m0 = mi * 64;
    const int n0w = nj * 32;  // N=128 stages (NTH=4)
    const int n0h = nj * 16;  // N=64 stages  (NTH=2)
    const int g = lane >> 2, q = lane & 3;

    float* sB2 = (float*)(smem + SB2_OFF);
    int* sSrc = (int*)(smem + SSRC_OFF);
    int* sDst = (int*)(smem + SDST_OFF);

    load_weight(smem, WU_OFF, Wue, 64, 64, STRIDE64, tid, ETHREADS);
    load_weight(smem, W3_OFF, We1, 64, 128, STRIDE128, tid, ETHREADS);
    load_weight(smem, W4_OFF, We2, 128, 128, STRIDE128, tid, ETHREADS);
    load_weight(smem, W5_OFF, Wc, 128, 64, STRIDE64, tid, ETHREADS);
    if (tid < 128) sB2[tid] = be1[tid];
    __syncthreads();

    for (int tile = blockIdx.x; tile < nTiles; tile += gridDim.x) {
        const int e0 = tile * M_TILE;
        __syncthreads();  // protect smem from previous iteration

        if (tid < M_TILE) {
            int eg = e0 + tid;
            if (eg >= E) eg = E - 1;
            sSrc[tid] = src[eg];
            sDst[tid] = dst[eg];
        }
        __syncthreads();

        // gather t = hs*hd -> ST (bf16 padded rows)
        for (int i = tid; i < M_TILE * 16; i += ETHREADS) {
            int e = i >> 4, d4 = i & 15;
            float4 a = ((const float4*)(h + (size_t)sSrc[e] * 64))[d4];
            float4 b = ((const float4*)(h + (size_t)sDst[e] * 64))[d4];
            *(uint2*)(smem + ST_OFF + e * STRIDE64 + d4 * 8) =
                pack4_bf16(a.x * b.x, a.y * b.y, a.z * b.z, a.w * b.w);
        }
        __syncthreads();

        // ---- stage 3: eh_new = 0.8*eh + 0.2*(t @ Wue) -> SE ----
        {
            // prefetch eh (DRAM stream) while MMA runs
            float2 pf[2][2][2][2];
#pragma unroll
            for (int hf = 0; hf < 2; ++hf)
#pragma unroll
                for (int mt = 0; mt < 2; ++mt)
#pragma unroll
                    for (int n = 0; n < 2; ++n) {
                        int col = n0h + n * 8 + q * 2;
                        int rA = m0 + hf * 32 + mt * 16 + g;
                        int egA = e0 + rA; if (egA >= E) egA = E - 1;
                        int egB = e0 + rA + 8; if (egB >= E) egB = E - 1;
                        pf[hf][mt][n][0] = *(const float2*)(eh + (size_t)egA * 64 + col);
                        pf[hf][mt][n][1] = *(const float2*)(eh + (size_t)egB * 64 + col);
                    }
            float a3[2][2][2][4];
            mma_stage2<4, 2>(sbase + ST_OFF, STRIDE64, sbase + WU_OFF, STRIDE64, m0, n0h, lane, a3);
#pragma unroll
            for (int hf = 0; hf < 2; ++hf)
#pragma unroll
                for (int mt = 0; mt < 2; ++mt)
#pragma unroll
                    for (int n = 0; n < 2; ++n) {
                        int col = n0h + n * 8 + q * 2;
                        int rA = m0 + hf * 32 + mt * 16 + g;
                        float2 evA = pf[hf][mt][n][0], evB = pf[hf][mt][n][1];
                        *(uint32_t*)(smem + SE_OFF + rA * STRIDE64 + col * 2) =
                            pack2_bf16(0.8f * evA.x + 0.2f * a3[hf][mt][n][0],
                                       0.8f * evA.y + 0.2f * a3[hf][mt][n][1]);
                        *(uint32_t*)(smem + SE_OFF + (rA + 8) * STRIDE64 + col * 2) =
                            pack2_bf16(0.8f * evB.x + 0.2f * a3[hf][mt][n][2],
                                       0.8f * evB.y + 0.2f * a3[hf][mt][n][3]);
                    }
        }
        __syncthreads();

        // ---- stage 4: x2 = relu(eh_new @ We1 + b2) -> SX ----
        {
            float acc[2][2][4][4];
            mma_stage2<4, 4>(sbase + SE_OFF, STRIDE64, sbase + W3_OFF, STRIDE128, m0, n0w, lane, acc);
#pragma unroll
            for (int hf = 0; hf < 2; ++hf)
#pragma unroll
                for (int mt = 0; mt < 2; ++mt)
#pragma unroll
                    for (int n = 0; n < 4; ++n) {
                        int col = n0w + n * 8 + q * 2;
                        float b0 = sB2[col], b1 = sB2[col + 1];
                        int rA = m0 + hf * 32 + mt * 16 + g;
                        *(uint32_t*)(smem + SX_OFF + rA * STRIDE128 + col * 2) =
                            pack2_bf16(fmaxf(acc[hf][mt][n][0] + b0, 0.f), fmaxf(acc[hf][mt][n][1] + b1, 0.f));
                        *(uint32_t*)(smem + SX_OFF + (rA + 8) * STRIDE128 + col * 2) =
                            pack2_bf16(fmaxf(acc[hf][mt][n][2] + b0, 0.f), fmaxf(acc[hf][mt][n][3] + b1, 0.f));
                    }
        }
        __syncthreads();

        // ---- stage 5: p = Y1[src] * (x2 @ We2) -> SX in place ----
        {
            float acc[2][2][4][4];
            mma_stage2<8, 4>(sbase + SX_OFF, STRIDE128, sbase + W4_OFF, STRIDE128, m0, n0w, lane, acc);
            __syncthreads();
#pragma unroll
            for (int hf = 0; hf < 2; ++hf)
#pragma unroll
                for (int mt = 0; mt < 2; ++mt)
#pragma unroll
                    for (int n = 0; n < 4; ++n) {
                        int col = n0w + n * 8 + q * 2;
                        int rA = m0 + hf * 32 + mt * 16 + g;
                        uint32_t mA = *(const uint32_t*)(g_Y1 + (size_t)sSrc[rA] * 128 + col);
                        uint32_t mB = *(const uint32_t*)(g_Y1 + (size_t)sSrc[rA + 8] * 128 + col);
                        __nv_bfloat162 hA = *(__nv_bfloat162*)&mA;
                        __nv_bfloat162 hB = *(__nv_bfloat162*)&mB;
                        *(uint32_t*)(smem + SX_OFF + rA * STRIDE128 + col * 2) =
                            pack2_bf16(acc[hf][mt][n][0] * __bfloat162float(hA.x),
                                       acc[hf][mt][n][1] * __bfloat162float(hA.y));
                        *(uint32_t*)(smem + SX_OFF + (rA + 8) * STRIDE128 + col * 2) =
                            pack2_bf16(acc[hf][mt][n][2] * __bfloat162float(hB.x),
                                       acc[hf][mt][n][3] * __bfloat162float(hB.y));
                    }
        }
        __syncthreads();

        // ---- stage 6: m = tanh(p @ Wc); vector reduce-add to out[dst] ----
        {
            float a6[2][2][2][4];
            mma_stage2<8, 2>(sbase + SX_OFF, STRIDE128, sbase + W5_OFF, STRIDE64, m0, n0h, lane, a6);
#pragma unroll
            for (int hf = 0; hf < 2; ++hf)
#pragma unroll
                for (int mt = 0; mt < 2; ++mt) {
                    int rA = m0 + hf * 32 + mt * 16 + g;
                    int egA = e0 + rA, egB = e0 + rA + 8;
                    int dA = sDst[rA], dB = sDst[rA + 8];
#pragma unroll
                    for (int n = 0; n < 2; ++n) {
                        int col = n0h + n * 8 + q * 2;
                        if (egA < E) {
                            float* p = out + (size_t)dA * 64 + col;
                            asm volatile("red.global.add.v2.f32 [%0], {%1,%2};"
                                :: "l"(p), "f"(tanhf(a6[hf][mt][n][0])), "f"(tanhf(a6[hf][mt][n][1])) : "memory");
                        }
                        if (egB < E) {
                            float* p = out + (size_t)dB * 64 + col;
                            asm volatile("red.global.add.v2.f32 [%0], {%1,%2};"
                                :: "l"(p), "f"(tanhf(a6[hf][mt][n][2])), "f"(tanhf(a6[hf][mt][n][3])) : "memory");
                        }
                    }
                }
        }
    }
}

extern "C" void kernel_launch(void* const* d_in, const int* in_sizes, int n_in,
                              void* d_out, int out_size) {
    const float* h   = (const float*)d_in[0];
    const float* eh  = (const float*)d_in[1];
    const float* Wn1 = (const float*)d_in[2];
    const float* bn1 = (const float*)d_in[3];
    const float* Wn2 = (const float*)d_in[4];
    const float* We1 = (const float*)d_in[5];
    const float* be1 = (const float*)d_in[6];
    const float* We2 = (const float*)d_in[7];
    const float* Wc  = (const float*)d_in[8];
    const float* Wue = (const float*)d_in[9];
    const int*   src = (const int*)d_in[10];
    const int*   dst = (const int*)d_in[11];
    float* out = (float*)d_out;

    int E = in_sizes[10];
    int Nn = in_sizes[0] / 64;
    if (Nn > N_MAX) Nn = N_MAX;
    int n4 = out_size / 4;
    int nTiles = (E + M_TILE - 1) / M_TILE;

    int init_blocks = (n4 + 255) / 256;
    if (init_blocks > 3125) init_blocks = 3125;
    init_out<<<init_blocks, 256>>>((const float4*)h, (float4*)out, n4);

    cudaFuncSetAttribute(node_kernel, cudaFuncAttributeMaxDynamicSharedMemorySize, NSMEM_BYTES);
    node_kernel<<<(Nn + 127) / 128, NTHREADS, NSMEM_BYTES>>>(h, Wn1, bn1, Wn2, Nn);

    int nSM = 148;
    cudaDeviceGetAttribute(&nSM, cudaDevAttrMultiProcessorCount, 0);
    int grid = nSM < nTiles ? nSM : nTiles;

    cudaFuncSetAttribute(edge_kernel, cudaFuncAttributeMaxDynamicSharedMemorySize, ESMEM_BYTES);
    edge_kernel<<<grid, ETHREADS, ESMEM_BYTES>>>(h, eh, We1, be1, We2, Wc, Wue,
                                                 src, dst, out, E, nTiles);
}

// round 8
// speedup vs baseline: 10.9284x; 1.1248x over previous
#include <cuda_runtime.h>
#include <cuda_bf16.h>
#include <math.h>
#include <stdint.h>

#define ETHREADS 256
#define NTHREADS 256
#define M_TILE 128
#define N_MAX 50000

#define STRIDE128 272
#define STRIDE64  144

// ---- padded bf16 weight images (edge-kernel streamed weights) ----
#define IWUE 0        // Wue [64x64]  s144 :  9216
#define IWE1 9216     // We1 [64x128] s272 : 17408
#define IWE2 26624    // We2 [128x128]s272 : 34816
#define IWC  61440    // Wc  [128x64] s144 : 18432
#define IMG_TOTAL 79872
__device__ __align__(16) unsigned char g_wimg[IMG_TOTAL];

// per-node m1 table: Y1 = relu(h@Wn1+b1)@Wn2, bf16 [N_MAX x 128]
__device__ __align__(16) __nv_bfloat16 g_Y1[(size_t)N_MAX * 128];

// ---- edge kernel smem (bytes) ----
#define WBUF_OFF 0          // 34816 (streamed weight, max = We2)
#define ST_OFF   34816      // 18432 (t -> eh_new in place)
#define SX_OFF   53248      // 34816 (x2 -> p in place)
#define SB2_OFF  88064      // 512
#define SSRC_OFF 88576      // 512
#define SDST_OFF 89088      // 512
#define ESMEM_BYTES 89600

// ---- node kernel smem ----
#define NW1_OFF 0
#define NW2_OFF (NW1_OFF + 64*STRIDE128)
#define NH_OFF  (NW2_OFF + 128*STRIDE128)
#define NX_OFF  (NH_OFF + 128*STRIDE64)
#define NB_OFF  (NX_OFF + 128*STRIDE128)
#define NSMEM_BYTES (NB_OFF + 512)

__global__ void init_out(const float4* __restrict__ h4, float4* __restrict__ o4, int n4) {
    int i = blockIdx.x * blockDim.x + threadIdx.x;
    int stride = gridDim.x * blockDim.x;
    for (int j = i; j < n4; j += stride) o4[j] = h4[j];
}

__device__ __forceinline__ uint32_t smem_u32(const void* p) {
    uint32_t a;
    asm("{ .reg .u64 t; cvta.to.shared.u64 t, %1; cvt.u32.u64 %0, t; }" : "=r"(a) : "l"(p));
    return a;
}
__device__ __forceinline__ uint32_t pack2_bf16(float a, float b) {
    __nv_bfloat162 p = __float22bfloat162_rn(make_float2(a, b));
    return *(unsigned int*)&p;
}
__device__ __forceinline__ uint2 pack4_bf16(float a, float b, float c, float d) {
    uint2 r; r.x = pack2_bf16(a, b); r.y = pack2_bf16(c, d); return r;
}
__device__ __forceinline__ float fast_tanh(float x) {
    float y;
    asm("tanh.approx.f32 %0, %1;" : "=f"(y) : "f"(x));
    return y;
}
__device__ __forceinline__ void ldsm_x4(uint32_t addr, uint32_t r[4]) {
    asm volatile("ldmatrix.sync.aligned.m8n8.x4.shared.b16 {%0,%1,%2,%3}, [%4];"
        : "=r"(r[0]), "=r"(r[1]), "=r"(r[2]), "=r"(r[3]) : "r"(addr));
}
__device__ __forceinline__ void ldsm_x4t(uint32_t addr, uint32_t r[4]) {
    asm volatile("ldmatrix.sync.aligned.m8n8.x4.trans.shared.b16 {%0,%1,%2,%3}, [%4];"
        : "=r"(r[0]), "=r"(r[1]), "=r"(r[2]), "=r"(r[3]) : "r"(addr));
}
__device__ __forceinline__ void mma16816(float d[4], const uint32_t a[4], const uint32_t b[2]) {
    asm volatile("mma.sync.aligned.m16n8k16.row.col.f32.bf16.bf16.f32 "
        "{%0,%1,%2,%3},{%4,%5,%6,%7},{%8,%9},{%0,%1,%2,%3};"
        : "+f"(d[0]), "+f"(d[1]), "+f"(d[2]), "+f"(d[3])
        : "r"(a[0]), "r"(a[1]), "r"(a[2]), "r"(a[3]), "r"(b[0]), "r"(b[1]));
}

// cp.async weight stream: copy padded image -> WBUF, then commit
__device__ __forceinline__ void cp_w(uint32_t sdst, int img_off, int bytes, int tid) {
    const unsigned char* gsrc = g_wimg + img_off;
    for (int i = tid * 16; i < bytes; i += ETHREADS * 16)
        asm volatile("cp.async.cg.shared.global [%0], [%1], 16;"
                     :: "r"(sdst + i), "l"(gsrc + i));
    asm volatile("cp.async.commit_group;");
}
#define CP_WAIT0() asm volatile("cp.async.wait_group 0;" ::: "memory")

// warp covers 64 rows (2 halves x 2 m16 tiles), B frags reused across halves
template<int KT, int NTH>
__device__ __forceinline__ void mma_stage2(uint32_t aAddr, int aStride,
                                           uint32_t wAddr, int wStride,
                                           int m0, int n0, int lane,
                                           float acc[2][2][NTH][4]) {
#pragma unroll
    for (int hf = 0; hf < 2; ++hf)
#pragma unroll
        for (int mt = 0; mt < 2; ++mt)
#pragma unroll
            for (int n = 0; n < NTH; ++n)
#pragma unroll
                for (int e = 0; e < 4; ++e) acc[hf][mt][n][e] = 0.f;
    const int krow = lane & 15;
    const int xoff = (lane >> 4) << 3;
#pragma unroll
    for (int k = 0; k < KT; ++k) {
        uint32_t b[NTH / 2][4];
#pragma unroll
        for (int np = 0; np < NTH / 2; ++np)
            ldsm_x4t(wAddr + (uint32_t)(k * 16 + krow) * wStride + (uint32_t)(n0 + np * 16 + xoff) * 2, b[np]);
#pragma unroll
        for (int hf = 0; hf < 2; ++hf) {
            uint32_t a[2][4];
#pragma unroll
            for (int mt = 0; mt < 2; ++mt)
                ldsm_x4(aAddr + (uint32_t)(m0 + hf * 32 + mt * 16 + krow) * aStride + (uint32_t)(k * 16 + xoff) * 2, a[mt]);
#pragma unroll
            for (int np = 0; np < NTH / 2; ++np) {
                mma16816(acc[hf][0][np * 2 + 0], a[0], b[np] + 0);
                mma16816(acc[hf][1][np * 2 + 0], a[1], b[np] + 0);
                mma16816(acc[hf][0][np * 2 + 1], a[0], b[np] + 2);
                mma16816(acc[hf][1][np * 2 + 1], a[1], b[np] + 2);
            }
        }
    }
}

// single-strip version for node kernel
template<int KT, int NTH>
__device__ __forceinline__ void mma_stage(uint32_t aAddr, int aStride,
                                          uint32_t wAddr, int wStride,
                                          int m0, int n0, int lane,
                                          float acc[2][NTH][4]) {
#pragma unroll
    for (int mt = 0; mt < 2; ++mt)
#pragma unroll
        for (int n = 0; n < NTH; ++n)
#pragma unroll
            for (int e = 0; e < 4; ++e) acc[mt][n][e] = 0.f;
    const int krow = lane & 15;
    const int xoff = (lane >> 4) << 3;
#pragma unroll
    for (int k = 0; k < KT; ++k) {
        uint32_t a[2][4];
#pragma unroll
        for (int mt = 0; mt < 2; ++mt)
            ldsm_x4(aAddr + (uint32_t)(m0 + mt * 16 + krow) * aStride + (uint32_t)(k * 16 + xoff) * 2, a[mt]);
#pragma unroll
        for (int np = 0; np < NTH / 2; ++np) {
            uint32_t b[4];
            ldsm_x4t(wAddr + (uint32_t)(k * 16 + krow) * wStride + (uint32_t)(n0 + np * 16 + xoff) * 2, b);
            mma16816(acc[0][np * 2 + 0], a[0], b + 0);
            mma16816(acc[1][np * 2 + 0], a[1], b + 0);
            mma16816(acc[0][np * 2 + 1], a[0], b + 2);
            mma16816(acc[1][np * 2 + 1], a[1], b + 2);
        }
    }
}

__device__ __forceinline__ void load_weight_smem(char* smemc, int off, const float* __restrict__ W,
                                                 int K, int N, int stride, int tid, int nthr) {
    int n4 = (K * N) >> 2;
    for (int i = tid; i < n4; i += nthr) {
        int idx = i << 2;
        int r = idx / N, c = idx % N;
        float4 v = *(const float4*)(W + idx);
        *(uint2*)(smemc + off + r * stride + c * 2) = pack4_bf16(v.x, v.y, v.z, v.w);
    }
}

// fp32 [K,N] -> padded bf16 global image
__global__ void convert_weights(const float* __restrict__ Wue, const float* __restrict__ We1,
                                const float* __restrict__ We2, const float* __restrict__ Wc) {
    int i = blockIdx.x * blockDim.x + threadIdx.x;
    if (i < 4096) {                 // Wue 64x64 s144
        int r = i >> 6, c = i & 63;
        *(__nv_bfloat16*)(g_wimg + IWUE + r * STRIDE64 + c * 2) = __float2bfloat16(Wue[i]);
    } else if (i < 12288) {         // We1 64x128 s272
        int j = i - 4096, r = j >> 7, c = j & 127;
        *(__nv_bfloat16*)(g_wimg + IWE1 + r * STRIDE128 + c * 2) = __float2bfloat16(We1[j]);
    } else if (i < 28672) {         // We2 128x128 s272
        int j = i - 12288, r = j >> 7, c = j & 127;
        *(__nv_bfloat16*)(g_wimg + IWE2 + r * STRIDE128 + c * 2) = __float2bfloat16(We2[j]);
    } else if (i < 36864) {         // Wc 128x64 s144
        int j = i - 28672, r = j >> 6, c = j & 63;
        *(__nv_bfloat16*)(g_wimg + IWC + r * STRIDE64 + c * 2) = __float2bfloat16(Wc[j]);
    }
}

// =============== node kernel: Y1 = relu(h@Wn1+b1)@Wn2 ===============
__global__ __launch_bounds__(NTHREADS)
void node_kernel(const float* __restrict__ h,
                 const float* __restrict__ Wn1, const float* __restrict__ bn1,
                 const float* __restrict__ Wn2, int Nn)
{
    extern __shared__ char smem[];
    const uint32_t sbase = smem_u32(smem);
    const int tid = threadIdx.x;
    const int warp = tid >> 5;
    const int lane = tid & 31;
    const int mi = warp >> 1, nj = warp & 1;
    const int m0 = mi * 32, n0 = nj * 64;
    const int g = lane >> 2, q = lane & 3;
    const int r0 = blockIdx.x * 128;

    float* sB = (float*)(smem + NB_OFF);
    load_weight_smem(smem, NW1_OFF, Wn1, 64, 128, STRIDE128, tid, NTHREADS);
    load_weight_smem(smem, NW2_OFF, Wn2, 128, 128, STRIDE128, tid, NTHREADS);
    if (tid < 128) sB[tid] = bn1[tid];

    for (int i = tid; i < 128 * 16; i += NTHREADS) {
        int r = i >> 4, d4 = i & 15;
        int nr = r0 + r; if (nr >= Nn) nr = Nn - 1;
        float4 v = ((const float4*)(h + (size_t)nr * 64))[d4];
        *(uint2*)(smem + NH_OFF + r * STRIDE64 + d4 * 8) = pack4_bf16(v.x, v.y, v.z, v.w);
    }
    __syncthreads();

    float acc[2][8][4];
    mma_stage<4, 8>(sbase + NH_OFF, STRIDE64, sbase + NW1_OFF, STRIDE128, m0, n0, lane, acc);
#pragma unroll
    for (int mt = 0; mt < 2; ++mt)
#pragma unroll
        for (int n = 0; n < 8; ++n) {
            int col = n0 + n * 8 + q * 2;
            float b0 = sB[col], b1 = sB[col + 1];
            int rA = m0 + mt * 16 + g;
            *(uint32_t*)(smem + NX_OFF + rA * STRIDE128 + col * 2) =
                pack2_bf16(fmaxf(acc[mt][n][0] + b0, 0.f), fmaxf(acc[mt][n][1] + b1, 0.f));
            *(uint32_t*)(smem + NX_OFF + (rA + 8) * STRIDE128 + col * 2) =
                pack2_bf16(fmaxf(acc[mt][n][2] + b0, 0.f), fmaxf(acc[mt][n][3] + b1, 0.f));
        }
    __syncthreads();

    mma_stage<8, 8>(sbase + NX_OFF, STRIDE128, sbase + NW2_OFF, STRIDE128, m0, n0, lane, acc);
#pragma unroll
    for (int mt = 0; mt < 2; ++mt)
#pragma unroll
        for (int n = 0; n < 8; ++n) {
            int col = n0 + n * 8 + q * 2;
            int rA = m0 + mt * 16 + g;
            int nrA = r0 + rA, nrB = r0 + rA + 8;
            if (nrA < Nn)
                *(uint32_t*)(g_Y1 + (size_t)nrA * 128 + col) = pack2_bf16(acc[mt][n][0], acc[mt][n][1]);
            if (nrB < Nn)
                *(uint32_t*)(g_Y1 + (size_t)nrB * 128 + col) = pack2_bf16(acc[mt][n][2], acc[mt][n][3]);
        }
}

// =============== edge kernel: 2 CTAs/SM, streamed weights ===============
__global__ __launch_bounds__(ETHREADS, 2)
void edge_kernel(const float* __restrict__ h, const float* __restrict__ eh,
                 const float* __restrict__ be1,
                 const int* __restrict__ src, const int* __restrict__ dst,
                 float* __restrict__ out, int E, int nTiles)
{
    extern __shared__ char smem[];
    const uint32_t sbase = smem_u32(smem);
    const int tid = threadIdx.x;
    const int warp = tid >> 5;
    const int lane = tid & 31;

    // 8 warps: 2 M-strips (64 rows) x 4 N-quarters
    const int mi = warp >> 2;
    const int nj = warp & 3;
    const int m0 = mi * 64;
    const int n0w = nj * 32;  // N=128 (NTH=4)
    const int n0h = nj * 16;  // N=64  (NTH=2)
    const int g = lane >> 2, q = lane & 3;

    float* sB2 = (float*)(smem + SB2_OFF);
    int* sSrc = (int*)(smem + SSRC_OFF);
    int* sDst = (int*)(smem + SDST_OFF);

    if (tid < 128) sB2[tid] = be1[tid];

    // prefetch first tile's indices
    int nxt_s = 0, nxt_d = 0;
    if (tid < M_TILE) {
        long e = (long)blockIdx.x * M_TILE + tid;
        int eg = (e < E) ? (int)e : E - 1;
        nxt_s = src[eg]; nxt_d = dst[eg];
    }

    for (int tile = blockIdx.x; tile < nTiles; tile += gridDim.x) {
        const int e0 = tile * M_TILE;
        __syncthreads();   // [1] prev tile fully done (WBUF/ST/SX/idx free)

        if (tid < M_TILE) { sSrc[tid] = nxt_s; sDst[tid] = nxt_d; }
        cp_w(sbase + WBUF_OFF, IWUE, 9216, tid);   // Wue stream (overlaps idx+gather)
        __syncthreads();   // [2] indices visible

        // prefetch indices for tile+grid (latency hidden across whole tile)
        if (tid < M_TILE) {
            long ne = (long)(tile + gridDim.x) * M_TILE + tid;
            int eg = (ne < E) ? (int)ne : E - 1;
            nxt_s = src[eg]; nxt_d = dst[eg];
        }

        // gather t = hs*hd -> ST
        for (int i = tid; i < M_TILE * 16; i += ETHREADS) {
            int e = i >> 4, d4 = i & 15;
            float4 a = ((const float4*)(h + (size_t)sSrc[e] * 64))[d4];
            float4 b = ((const float4*)(h + (size_t)sDst[e] * 64))[d4];
            *(uint2*)(smem + ST_OFF + e * STRIDE64 + d4 * 8) =
                pack4_bf16(a.x * b.x, a.y * b.y, a.z * b.z, a.w * b.w);
        }
        CP_WAIT0();
        __syncthreads();   // [3] t + Wue ready

        // ---- stage 3: eh_new = 0.8*eh + 0.2*(t @ Wue), in place -> ST ----
        {
            float2 pf[2][2][2][2];
#pragma unroll
            for (int hf = 0; hf < 2; ++hf)
#pragma unroll
                for (int mt = 0; mt < 2; ++mt)
#pragma unroll
                    for (int n = 0; n < 2; ++n) {
                        int col = n0h + n * 8 + q * 2;
                        int rA = m0 + hf * 32 + mt * 16 + g;
                        int egA = e0 + rA; if (egA >= E) egA = E - 1;
                        int egB = e0 + rA + 8; if (egB >= E) egB = E - 1;
                        pf[hf][mt][n][0] = *(const float2*)(eh + (size_t)egA * 64 + col);
                        pf[hf][mt][n][1] = *(const float2*)(eh + (size_t)egB * 64 + col);
                    }
            float a3[2][2][2][4];
            mma_stage2<4, 2>(sbase + ST_OFF, STRIDE64, sbase + WBUF_OFF, STRIDE64, m0, n0h, lane, a3);
            __syncthreads();   // [4] all t reads done before in-place write
            cp_w(sbase + WBUF_OFF + 0, IWE1, 17408, tid);   // We1 stream (overlaps epilogue)
#pragma unroll
            for (int hf = 0; hf < 2; ++hf)
#pragma unroll
                for (int mt = 0; mt < 2; ++mt)
#pragma unroll
                    for (int n = 0; n < 2; ++n) {
                        int col = n0h + n * 8 + q * 2;
                        int rA = m0 + hf * 32 + mt * 16 + g;
                        float2 evA = pf[hf][mt][n][0], evB = pf[hf][mt][n][1];
                        *(uint32_t*)(smem + ST_OFF + rA * STRIDE64 + col * 2) =
                            pack2_bf16(0.8f * evA.x + 0.2f * a3[hf][mt][n][0],
                                       0.8f * evA.y + 0.2f * a3[hf][mt][n][1]);
                        *(uint32_t*)(smem + ST_OFF + (rA + 8) * STRIDE64 + col * 2) =
                            pack2_bf16(0.8f * evB.x + 0.2f * a3[hf][mt][n][2],
                                       0.8f * evB.y + 0.2f * a3[hf][mt][n][3]);
                    }
        }
        CP_WAIT0();
        __syncthreads();   // [5] eh_new + We1 ready

        // ---- stage 4: x2 = relu(eh_new @ We1 + b2) -> SX ----
        {
            float acc[2][2][4][4];
            mma_stage2<4, 4>(sbase + ST_OFF, STRIDE64, sbase + WBUF_OFF, STRIDE128, m0, n0w, lane, acc);
            __syncthreads();   // [6] We1 reads done
            cp_w(sbase + WBUF_OFF, IWE2, 34816, tid);       // We2 stream
#pragma unroll
            for (int hf = 0; hf < 2; ++hf)
#pragma unroll
                for (int mt = 0; mt < 2; ++mt)
#pragma unroll
                    for (int n = 0; n < 4; ++n) {
                        int col = n0w + n * 8 + q * 2;
                        float b0 = sB2[col], b1 = sB2[col + 1];
                        int rA = m0 + hf * 32 + mt * 16 + g;
                        *(uint32_t*)(smem + SX_OFF + rA * STRIDE128 + col * 2) =
                            pack2_bf16(fmaxf(acc[hf][mt][n][0] + b0, 0.f), fmaxf(acc[hf][mt][n][1] + b1, 0.f));
                        *(uint32_t*)(smem + SX_OFF + (rA + 8) * STRIDE128 + col * 2) =
                            pack2_bf16(fmaxf(acc[hf][mt][n][2] + b0, 0.f), fmaxf(acc[hf][mt][n][3] + b1, 0.f));
                    }
        }
        CP_WAIT0();
        __syncthreads();   // [7] x2 + We2 ready

        // ---- stage 5: p = Y1[src] * (x2 @ We2), in place -> SX ----
        {
            float acc[2][2][4][4];
            mma_stage2<8, 4>(sbase + SX_OFF, STRIDE128, sbase + WBUF_OFF, STRIDE128, m0, n0w, lane, acc);
            __syncthreads();   // [8] x2 + We2 reads done
            cp_w(sbase + WBUF_OFF, IWC, 18432, tid);        // Wc stream
#pragma unroll
            for (int hf = 0; hf < 2; ++hf)
#pragma unroll
                for (int mt = 0; mt < 2; ++mt)
#pragma unroll
                    for (int n = 0; n < 4; ++n) {
                        int col = n0w + n * 8 + q * 2;
                        int rA = m0 + hf * 32 + mt * 16 + g;
                        uint32_t mA = *(const uint32_t*)(g_Y1 + (size_t)sSrc[rA] * 128 + col);
                        uint32_t mB = *(const uint32_t*)(g_Y1 + (size_t)sSrc[rA + 8] * 128 + col);
                        __nv_bfloat162 hA = *(__nv_bfloat162*)&mA;
                        __nv_bfloat162 hB = *(__nv_bfloat162*)&mB;
                        *(uint32_t*)(smem + SX_OFF + rA * STRIDE128 + col * 2) =
                            pack2_bf16(acc[hf][mt][n][0] * __bfloat162float(hA.x),
                                       acc[hf][mt][n][1] * __bfloat162float(hA.y));
                        *(uint32_t*)(smem + SX_OFF + (rA + 8) * STRIDE128 + col * 2) =
                            pack2_bf16(acc[hf][mt][n][2] * __bfloat162float(hB.x),
                                       acc[hf][mt][n][3] * __bfloat162float(hB.y));
                    }
        }
        CP_WAIT0();
        __syncthreads();   // [9] p + Wc ready

        // ---- stage 6: m = tanh(p @ Wc); reduce-add to out[dst] ----
        {
            float a6[2][2][2][4];
            mma_stage2<8, 2>(sbase + SX_OFF, STRIDE128, sbase + WBUF_OFF, STRIDE64, m0, n0h, lane, a6);
#pragma unroll
            for (int hf = 0; hf < 2; ++hf)
#pragma unroll
                for (int mt = 0; mt < 2; ++mt) {
                    int rA = m0 + hf * 32 + mt * 16 + g;
                    int egA = e0 + rA, egB = e0 + rA + 8;
                    int dA = sDst[rA], dB = sDst[rA + 8];
#pragma unroll
                    for (int n = 0; n < 2; ++n) {
                        int col = n0h + n * 8 + q * 2;
                        if (egA < E) {
                            float* p = out + (size_t)dA * 64 + col;
                            asm volatile("red.global.add.v2.f32 [%0], {%1,%2};"
                                :: "l"(p), "f"(fast_tanh(a6[hf][mt][n][0])), "f"(fast_tanh(a6[hf][mt][n][1])) : "memory");
                        }
                        if (egB < E) {
                            float* p = out + (size_t)dB * 64 + col;
                            asm volatile("red.global.add.v2.f32 [%0], {%1,%2};"
                                :: "l"(p), "f"(fast_tanh(a6[hf][mt][n][2])), "f"(fast_tanh(a6[hf][mt][n][3])) : "memory");
                        }
                    }
                }
        }
    }
}

extern "C" void kernel_launch(void* const* d_in, const int* in_sizes, int n_in,
                              void* d_out, int out_size) {
    const float* h   = (const float*)d_in[0];
    const float* eh  = (const float*)d_in[1];
    const float* Wn1 = (const float*)d_in[2];
    const float* bn1 = (const float*)d_in[3];
    const float* Wn2 = (const float*)d_in[4];
    const float* We1 = (const float*)d_in[5];
    const float* be1 = (const float*)d_in[6];
    const float* We2 = (const float*)d_in[7];
    const float* Wc  = (const float*)d_in[8];
    const float* Wue = (const float*)d_in[9];
    const int*   src = (const int*)d_in[10];
    const int*   dst = (const int*)d_in[11];
    float* out = (float*)d_out;

    int E = in_sizes[10];
    int Nn = in_sizes[0] / 64;
    if (Nn > N_MAX) Nn = N_MAX;
    int n4 = out_size / 4;
    int nTiles = (E + M_TILE - 1) / M_TILE;

    convert_weights<<<(36864 + 255) / 256, 256>>>(Wue, We1, We2, Wc);

    int init_blocks = (n4 + 255) / 256;
    if (init_blocks > 3125) init_blocks = 3125;
    init_out<<<init_blocks, 256>>>((const float4*)h, (float4*)out, n4);

    cudaFuncSetAttribute(node_kernel, cudaFuncAttributeMaxDynamicSharedMemorySize, NSMEM_BYTES);
    node_kernel<<<(Nn + 127) / 128, NTHREADS, NSMEM_BYTES>>>(h, Wn1, bn1, Wn2, Nn);

    int nSM = 148;
    cudaDeviceGetAttribute(&nSM, cudaDevAttrMultiProcessorCount, 0);
    int grid = 2 * nSM;
    if (grid > nTiles) grid = nTiles;

    cudaFuncSetAttribute(edge_kernel, cudaFuncAttributeMaxDynamicSharedMemorySize, ESMEM_BYTES);
    edge_kernel<<<grid, ETHREADS, ESMEM_BYTES>>>(h, eh, be1, src, dst, out, E, nTiles);
}